// round 9
// baseline (speedup 1.0000x reference)
#include <cuda_runtime.h>
#include <cuda_bf16.h>
#include <math.h>

#define S_LEN   2048
#define D_DIM   64
#define TQ      32
#define NBH     32
#define KVSTR   36        // u32 words per token row (32 data + 4 pad; LDSM-clean)
#define REDSTR  68

// ---- main-kernel shared memory word offsets ----
#define OFF_Q    0                     // 32*68 = 2176
#define ARR_W    4608                  // 128 tokens * 36 words
#define BUF_W    (4*ARR_W)             // KH,KL,VH,VL = 18432 words per buffer
#define OFF_BUF  2176                  // two buffers: 2*18432 = 36864
#define OFF_PART (OFF_BUF + 2*BUF_W)   // 39040 : 32*8
#define OFF_INV  (OFF_PART + 256)      // 39296 : 32
#define SMEM_WORDS (OFF_INV + 32)      // 39328 words = 157312 bytes
#define OFF_RED  OFF_BUF               // O-reduction overlay: 8*32*68 = 17408 words

// ---- global scratch ----
__device__ __align__(16) unsigned g_KH[(size_t)NBH * S_LEN * KVSTR];
__device__ __align__(16) unsigned g_KL[(size_t)NBH * S_LEN * KVSTR];
__device__ __align__(16) unsigned g_VH[(size_t)NBH * S_LEN * KVSTR];
__device__ __align__(16) unsigned g_VL[(size_t)NBH * S_LEN * KVSTR];
__device__ unsigned g_mpack[(size_t)S_LEN * (S_LEN / 32)];   // 1 bit per mask elem

__device__ __forceinline__ void cvt_hilo2(float x, float y, unsigned &h, unsigned &l) {
    __nv_bfloat162 hh = __floats2bfloat162_rn(x, y);
    float rx = x - __bfloat162float(hh.x);
    float ry = y - __bfloat162float(hh.y);
    __nv_bfloat162 ll = __floats2bfloat162_rn(rx, ry);
    h = *reinterpret_cast<unsigned*>(&hh);
    l = *reinterpret_cast<unsigned*>(&ll);
}

#define MMA16816(C, A0, A1, A2, A3, B0, B1)                                        \
    asm volatile("mma.sync.aligned.m16n8k16.row.col.f32.bf16.bf16.f32 "            \
                 "{%0,%1,%2,%3},{%4,%5,%6,%7},{%8,%9},{%0,%1,%2,%3};\n"            \
                 : "+f"(C[0]), "+f"(C[1]), "+f"(C[2]), "+f"(C[3])                  \
                 : "r"(A0), "r"(A1), "r"(A2), "r"(A3), "r"(B0), "r"(B1))

#define LDSM_X4(R0, R1, R2, R3, ADDR)                                              \
    asm volatile("ldmatrix.sync.aligned.m8n8.x4.shared.b16 {%0,%1,%2,%3}, [%4];"  \
                 : "=r"(R0), "=r"(R1), "=r"(R2), "=r"(R3) : "r"(ADDR))

#define LDSM_X4_T(R0, R1, R2, R3, ADDR)                                            \
    asm volatile("ldmatrix.sync.aligned.m8n8.x4.trans.shared.b16 {%0,%1,%2,%3}, [%4];" \
                 : "=r"(R0), "=r"(R1), "=r"(R2), "=r"(R3) : "r"(ADDR))

#define CP_ASYNC16(SADDR, GPTR)                                                    \
    asm volatile("cp.async.cg.shared.global [%0], [%1], 16;\n" :: "r"(SADDR), "l"(GPTR))
#define CP_COMMIT()  asm volatile("cp.async.commit_group;\n")
#define CP_WAIT0()   asm volatile("cp.async.wait_group 0;\n" ::: "memory")
#define CP_WAIT1()   asm volatile("cp.async.wait_group 1;\n" ::: "memory")

// ===================== pre-pass 1: convert K,V -> bf16 hi/lo scratch ============
__global__ void __launch_bounds__(256)
preconvert_kv(const float* __restrict__ K, const float* __restrict__ V)
{
    const int bh  = blockIdx.y;
    const int idx = blockIdx.x * 256 + threadIdx.x;
    const int token = idx >> 4, c4 = idx & 15;
    const size_t tok = (size_t)bh * S_LEN + token;
    const size_t go  = tok * KVSTR + c4 * 2;

    unsigned h0, l0, h1, l1;
    float4 k = __ldg((const float4*)(K + tok * D_DIM) + c4);
    cvt_hilo2(k.x, k.y, h0, l0);
    cvt_hilo2(k.z, k.w, h1, l1);
    *(uint2*)&g_KH[go] = make_uint2(h0, h1);
    *(uint2*)&g_KL[go] = make_uint2(l0, l1);

    float4 v = __ldg((const float4*)(V + tok * D_DIM) + c4);
    cvt_hilo2(v.x, v.y, h0, l0);
    cvt_hilo2(v.z, v.w, h1, l1);
    *(uint2*)&g_VH[go] = make_uint2(h0, h1);
    *(uint2*)&g_VL[go] = make_uint2(l0, l1);
}

// ===================== pre-pass 2: pack mask to 1 bit/elem ======================
__global__ void __launch_bounds__(256)
pack_mask(const unsigned* __restrict__ M)
{
    const int lane = threadIdx.x & 31;
    const int wglob = (blockIdx.x * 256 + threadIdx.x) >> 5;
    const int nwarps = (gridDim.x * 256) >> 5;
    for (int w = wglob; w < S_LEN * (S_LEN / 32); w += nwarps) {
        unsigned bit = (M[(size_t)w * 32 + lane] != 0u) ? 1u : 0u;
        unsigned word = __ballot_sync(0xffffffffu, bit);
        if (lane == 0) g_mpack[w] = word;
    }
}

// ===================== main fused attention kernel ==============================
__global__ void __launch_bounds__(256, 1)
attn_flash_kernel(const float* __restrict__ Q,
                  float* __restrict__ p_val,
                  float* __restrict__ p_attn)
{
    extern __shared__ float smem[];
    const unsigned smem_u32 = (unsigned)__cvta_generic_to_shared(smem);

    const int tid  = threadIdx.x;
    const int warp = tid >> 5;
    const int lane = tid & 31;
    const int g    = lane >> 2;
    const int tg   = lane & 3;
    const int bh   = blockIdx.y;
    const int q0   = blockIdx.x * TQ;
    const int ln0  = warp * 16;

    // ---- ldmatrix per-lane byte addresses (buffer 0) ----
    const int qk_row  = ln0 + ((lane >> 4) << 3) + (lane & 7);
    const unsigned qk_off = (unsigned)(qk_row * KVSTR + (((lane >> 3) & 1) << 2)) * 4u;
    const unsigned kh_base = smem_u32 + (OFF_BUF + 0 * ARR_W) * 4u + qk_off;
    const unsigned kl_base = smem_u32 + (OFF_BUF + 1 * ARR_W) * 4u + qk_off;
    const int pv_row  = ln0 + (((lane >> 3) & 1) << 3) + (lane & 7);
    const unsigned pv_off = (unsigned)(pv_row * KVSTR + ((lane >> 4) << 2)) * 4u;
    const unsigned vh_base = smem_u32 + (OFF_BUF + 2 * ARR_W) * 4u + pv_off;
    const unsigned vl_base = smem_u32 + (OFF_BUF + 3 * ARR_W) * 4u + pv_off;

    // ================= Q tile (32 rows) -> smem -> A fragments =================
    {
#pragma unroll
        for (int i = 0; i < 2; i++) {
            int idx = tid + i * 256;
            int row = idx >> 4, c4 = idx & 15;
            float4 qv = __ldg((const float4*)(Q + ((size_t)bh * S_LEN + q0 + row) * D_DIM) + c4);
            *((float4*)(smem + OFF_Q + row * 68 + c4 * 4)) = qv;
        }
    }
    __syncthreads();

    unsigned qah[2][4][4], qal[2][4][4];
#pragma unroll
    for (int m = 0; m < 2; m++) {
        int r0 = m * 16 + g, r1 = m * 16 + g + 8;
#pragma unroll
        for (int ks = 0; ks < 4; ks++) {
            int c = ks * 16 + tg * 2;
            float2 x0 = *(const float2*)(smem + OFF_Q + r0 * 68 + c);
            float2 x1 = *(const float2*)(smem + OFF_Q + r1 * 68 + c);
            float2 x2 = *(const float2*)(smem + OFF_Q + r0 * 68 + c + 8);
            float2 x3 = *(const float2*)(smem + OFF_Q + r1 * 68 + c + 8);
            cvt_hilo2(x0.x, x0.y, qah[m][ks][0], qal[m][ks][0]);
            cvt_hilo2(x1.x, x1.y, qah[m][ks][1], qal[m][ks][1]);
            cvt_hilo2(x2.x, x2.y, qah[m][ks][2], qal[m][ks][2]);
            cvt_hilo2(x3.x, x3.y, qah[m][ks][3], qal[m][ks][3]);
        }
    }

    // mask word pointers (one broadcast word per row per stage) and p_attn rows
    const unsigned* mp[4];
    float* pa[4];
#pragma unroll
    for (int r = 0; r < 4; r++) {
        int row = (r >> 1) * 16 + g + (r & 1) * 8;    // g, g+8, 16+g, 24+g
        mp[r] = g_mpack + (size_t)(q0 + row) * 64 + (warp >> 1);
        pa[r] = p_attn + ((size_t)bh * S_LEN + q0 + row) * S_LEN;
    }
    const unsigned posbase = (warp & 1) * 16;
    const size_t bh_base = (size_t)bh * S_LEN * KVSTR;

    float rs[4] = {0.f, 0.f, 0.f, 0.f};

    // =========================================================================
    // PHASE A: K-only pass -> rowsums
    // =========================================================================
    {   // prologue: K0
        for (int i = tid; i < ARR_W / 4; i += 256) {
            unsigned so = (unsigned)(OFF_BUF * 4 + i * 16);
            CP_ASYNC16(smem_u32 + so,             (const uint4*)(g_KH + bh_base) + i);
            CP_ASYNC16(smem_u32 + so + ARR_W * 4, (const uint4*)(g_KL + bh_base) + i);
        }
        CP_COMMIT();
    }

    for (int st = 0; st < 16; st++) {
        const unsigned bufoff = (unsigned)(st & 1) * (BUF_W * 4);
        CP_WAIT0();
        __syncthreads();

        if (st < 15) {
            const size_t sb = bh_base + (size_t)(st + 1) * 128 * KVSTR;
            const unsigned dst = (unsigned)(OFF_BUF * 4) + (unsigned)((st + 1) & 1) * (BUF_W * 4);
            for (int i = tid; i < ARR_W / 4; i += 256) {
                unsigned so = dst + (unsigned)i * 16u;
                CP_ASYNC16(smem_u32 + so,             (const uint4*)(g_KH + sb) + i);
                CP_ASYNC16(smem_u32 + so + ARR_W * 4, (const uint4*)(g_KL + sb) + i);
            }
            CP_COMMIT();
        }

        float C00[4] = {0,0,0,0}, C01[4] = {0,0,0,0};
        float C10[4] = {0,0,0,0}, C11[4] = {0,0,0,0};
#pragma unroll
        for (int ks = 0; ks < 4; ks++) {
            unsigned b0, b1, b2, b3, l0, l1, l2, l3;
            LDSM_X4(b0, b1, b2, b3, kh_base + bufoff + ks * 32u);
            LDSM_X4(l0, l1, l2, l3, kl_base + bufoff + ks * 32u);
            MMA16816(C00, qah[0][ks][0], qah[0][ks][1], qah[0][ks][2], qah[0][ks][3], b0, b1);
            MMA16816(C01, qah[0][ks][0], qah[0][ks][1], qah[0][ks][2], qah[0][ks][3], b2, b3);
            MMA16816(C10, qah[1][ks][0], qah[1][ks][1], qah[1][ks][2], qah[1][ks][3], b0, b1);
            MMA16816(C11, qah[1][ks][0], qah[1][ks][1], qah[1][ks][2], qah[1][ks][3], b2, b3);
            MMA16816(C00, qal[0][ks][0], qal[0][ks][1], qal[0][ks][2], qal[0][ks][3], b0, b1);
            MMA16816(C01, qal[0][ks][0], qal[0][ks][1], qal[0][ks][2], qal[0][ks][3], b2, b3);
            MMA16816(C10, qal[1][ks][0], qal[1][ks][1], qal[1][ks][2], qal[1][ks][3], b0, b1);
            MMA16816(C11, qal[1][ks][0], qal[1][ks][1], qal[1][ks][2], qal[1][ks][3], b2, b3);
            MMA16816(C00, qah[0][ks][0], qah[0][ks][1], qah[0][ks][2], qah[0][ks][3], l0, l1);
            MMA16816(C01, qah[0][ks][0], qah[0][ks][1], qah[0][ks][2], qah[0][ks][3], l2, l3);
            MMA16816(C10, qah[1][ks][0], qah[1][ks][1], qah[1][ks][2], qah[1][ks][3], l0, l1);
            MMA16816(C11, qah[1][ks][0], qah[1][ks][1], qah[1][ks][2], qah[1][ks][3], l2, l3);
        }

        unsigned mw0 = __ldg(mp[0] + st * 4);
        unsigned mw1 = __ldg(mp[1] + st * 4);
        unsigned mw2 = __ldg(mp[2] + st * 4);
        unsigned mw3 = __ldg(mp[3] + st * 4);
#pragma unroll
        for (int m = 0; m < 2; m++) {
            unsigned ma = m ? mw2 : mw0;
            unsigned mb = m ? mw3 : mw1;
#pragma unroll
            for (int t = 0; t < 2; t++) {
                const float* C = m ? (t ? C11 : C10) : (t ? C01 : C00);
                unsigned sh = posbase + t * 8 + tg * 2;
                float E0 = ((ma >> sh) & 1u)       ? 0.f : __expf(C[0] * 0.125f);
                float E1 = ((ma >> (sh + 1)) & 1u) ? 0.f : __expf(C[1] * 0.125f);
                float E2 = ((mb >> sh) & 1u)       ? 0.f : __expf(C[2] * 0.125f);
                float E3 = ((mb >> (sh + 1)) & 1u) ? 0.f : __expf(C[3] * 0.125f);
                rs[2 * m]     += E0 + E1;
                rs[2 * m + 1] += E2 + E3;
            }
        }
    }

    // ---- prologue for phase B: issue K0 and V0 now (buffer 0 is free) ----
    {
        for (int i = tid; i < ARR_W / 4; i += 256) {
            unsigned so = (unsigned)(OFF_BUF * 4 + i * 16);
            CP_ASYNC16(smem_u32 + so,             (const uint4*)(g_KH + bh_base) + i);
            CP_ASYNC16(smem_u32 + so + ARR_W * 4, (const uint4*)(g_KL + bh_base) + i);
        }
        CP_COMMIT();
        for (int i = tid; i < ARR_W / 4; i += 256) {
            unsigned so = (unsigned)(OFF_BUF * 4 + i * 16);
            CP_ASYNC16(smem_u32 + so + 2 * ARR_W * 4, (const uint4*)(g_VH + bh_base) + i);
            CP_ASYNC16(smem_u32 + so + 3 * ARR_W * 4, (const uint4*)(g_VL + bh_base) + i);
        }
        CP_COMMIT();
    }

    // ---- rowsum reduction -> inv (overlaps with prologue transfers) ----
#pragma unroll
    for (int r = 0; r < 4; r++) {
        rs[r] += __shfl_xor_sync(0xffffffff, rs[r], 1);
        rs[r] += __shfl_xor_sync(0xffffffff, rs[r], 2);
    }
    if (tg == 0) {
#pragma unroll
        for (int r = 0; r < 4; r++) {
            int row = (r >> 1) * 16 + g + (r & 1) * 8;
            smem[OFF_PART + row * 8 + warp] = rs[r];
        }
    }
    __syncthreads();
    if (tid < TQ) {
        float s = 0.f;
#pragma unroll
        for (int i = 0; i < 8; i++) s += smem[OFF_PART + tid * 8 + i];
        smem[OFF_INV + tid] = 1.0f / s;
    }
    __syncthreads();
    float invr[2][2];
#pragma unroll
    for (int m = 0; m < 2; m++) {
        invr[m][0] = smem[OFF_INV + m * 16 + g];
        invr[m][1] = smem[OFF_INV + m * 16 + g + 8];
    }

    float O[16][4];
#pragma unroll
    for (int j = 0; j < 16; j++) { O[j][0] = O[j][1] = O[j][2] = O[j][3] = 0.f; }

    // =========================================================================
    // PHASE B: QK again (identical order) -> normalized p_attn + PV
    // =========================================================================
    for (int st = 0; st < 16; st++) {
        const int kb0 = st * 128;
        const unsigned bufoff = (unsigned)(st & 1) * (BUF_W * 4);

        CP_WAIT1();          // K(st) ready; V(st) may still be in flight
        __syncthreads();

        if (st < 15) {       // prefetch K(st+1)
            const size_t sb = bh_base + (size_t)(kb0 + 128) * KVSTR;
            const unsigned dst = (unsigned)(OFF_BUF * 4) + (unsigned)((st + 1) & 1) * (BUF_W * 4);
            for (int i = tid; i < ARR_W / 4; i += 256) {
                unsigned so = dst + (unsigned)i * 16u;
                CP_ASYNC16(smem_u32 + so,             (const uint4*)(g_KH + sb) + i);
                CP_ASYNC16(smem_u32 + so + ARR_W * 4, (const uint4*)(g_KL + sb) + i);
            }
            CP_COMMIT();
        }

        float C00[4] = {0,0,0,0}, C01[4] = {0,0,0,0};
        float C10[4] = {0,0,0,0}, C11[4] = {0,0,0,0};
#pragma unroll
        for (int ks = 0; ks < 4; ks++) {
            unsigned b0, b1, b2, b3, l0, l1, l2, l3;
            LDSM_X4(b0, b1, b2, b3, kh_base + bufoff + ks * 32u);
            LDSM_X4(l0, l1, l2, l3, kl_base + bufoff + ks * 32u);
            MMA16816(C00, qah[0][ks][0], qah[0][ks][1], qah[0][ks][2], qah[0][ks][3], b0, b1);
            MMA16816(C01, qah[0][ks][0], qah[0][ks][1], qah[0][ks][2], qah[0][ks][3], b2, b3);
            MMA16816(C10, qah[1][ks][0], qah[1][ks][1], qah[1][ks][2], qah[1][ks][3], b0, b1);
            MMA16816(C11, qah[1][ks][0], qah[1][ks][1], qah[1][ks][2], qah[1][ks][3], b2, b3);
            MMA16816(C00, qal[0][ks][0], qal[0][ks][1], qal[0][ks][2], qal[0][ks][3], b0, b1);
            MMA16816(C01, qal[0][ks][0], qal[0][ks][1], qal[0][ks][2], qal[0][ks][3], b2, b3);
            MMA16816(C10, qal[1][ks][0], qal[1][ks][1], qal[1][ks][2], qal[1][ks][3], b0, b1);
            MMA16816(C11, qal[1][ks][0], qal[1][ks][1], qal[1][ks][2], qal[1][ks][3], b2, b3);
            MMA16816(C00, qah[0][ks][0], qah[0][ks][1], qah[0][ks][2], qah[0][ks][3], l0, l1);
            MMA16816(C01, qah[0][ks][0], qah[0][ks][1], qah[0][ks][2], qah[0][ks][3], l2, l3);
            MMA16816(C10, qah[1][ks][0], qah[1][ks][1], qah[1][ks][2], qah[1][ks][3], l0, l1);
            MMA16816(C11, qah[1][ks][0], qah[1][ks][1], qah[1][ks][2], qah[1][ks][3], l2, l3);
        }

        if (st < 15) { CP_WAIT1(); } else { CP_WAIT0(); }   // V(st) ready
        __syncthreads();

        if (st < 15) {       // prefetch V(st+1)
            const size_t sb = bh_base + (size_t)(kb0 + 128) * KVSTR;
            const unsigned dst = (unsigned)(OFF_BUF * 4) + (unsigned)((st + 1) & 1) * (BUF_W * 4);
            for (int i = tid; i < ARR_W / 4; i += 256) {
                unsigned so = dst + (unsigned)i * 16u;
                CP_ASYNC16(smem_u32 + so + 2 * ARR_W * 4, (const uint4*)(g_VH + sb) + i);
                CP_ASYNC16(smem_u32 + so + 3 * ARR_W * 4, (const uint4*)(g_VL + sb) + i);
            }
            CP_COMMIT();
        }

        // ---- epilogue: mask, exp, scale by inv, streaming store p_attn ----
        unsigned mw0 = __ldg(mp[0] + st * 4);
        unsigned mw1 = __ldg(mp[1] + st * 4);
        unsigned mw2 = __ldg(mp[2] + st * 4);
        unsigned mw3 = __ldg(mp[3] + st * 4);
        float e[2][2][4];
#pragma unroll
        for (int m = 0; m < 2; m++) {
            unsigned ma = m ? mw2 : mw0;
            unsigned mb = m ? mw3 : mw1;
#pragma unroll
            for (int t = 0; t < 2; t++) {
                const float* C = m ? (t ? C11 : C10) : (t ? C01 : C00);
                int nb = kb0 + ln0 + t * 8 + tg * 2;
                unsigned sh = posbase + t * 8 + tg * 2;
                float* E = e[m][t];
                E[0] = ((ma >> sh) & 1u)       ? 0.f : invr[m][0] * __expf(C[0] * 0.125f);
                E[1] = ((ma >> (sh + 1)) & 1u) ? 0.f : invr[m][0] * __expf(C[1] * 0.125f);
                E[2] = ((mb >> sh) & 1u)       ? 0.f : invr[m][1] * __expf(C[2] * 0.125f);
                E[3] = ((mb >> (sh + 1)) & 1u) ? 0.f : invr[m][1] * __expf(C[3] * 0.125f);
                __stcs((float2*)(pa[2 * m]     + nb), make_float2(E[0], E[1]));
                __stcs((float2*)(pa[2 * m + 1] + nb), make_float2(E[2], E[3]));
            }
        }

        // ---- E -> A-frag hi/lo (C-frag layout == A-frag layout) ----
        unsigned Ah[2][4], Al[2][4];
#pragma unroll
        for (int m = 0; m < 2; m++) {
            cvt_hilo2(e[m][0][0], e[m][0][1], Ah[m][0], Al[m][0]);
            cvt_hilo2(e[m][0][2], e[m][0][3], Ah[m][1], Al[m][1]);
            cvt_hilo2(e[m][1][0], e[m][1][1], Ah[m][2], Al[m][2]);
            cvt_hilo2(e[m][1][2], e[m][1][3], Ah[m][3], Al[m][3]);
        }

        // ---- PV (normalized): warp's 16 tokens x all 64 d ----
#pragma unroll
        for (int jp = 0; jp < 4; jp++) {
            unsigned b0, b1, b2, b3, l0, l1, l2, l3;
            LDSM_X4_T(b0, b1, b2, b3, vh_base + bufoff + jp * 32u);
            LDSM_X4_T(l0, l1, l2, l3, vl_base + bufoff + jp * 32u);
#pragma unroll
            for (int m = 0; m < 2; m++) {
                float* Oa = O[m * 8 + 2 * jp];
                float* Ob = O[m * 8 + 2 * jp + 1];
                MMA16816(Oa, Ah[m][0], Ah[m][1], Ah[m][2], Ah[m][3], b0, b1);
                MMA16816(Oa, Al[m][0], Al[m][1], Al[m][2], Al[m][3], b0, b1);
                MMA16816(Oa, Ah[m][0], Ah[m][1], Ah[m][2], Ah[m][3], l0, l1);
                MMA16816(Ob, Ah[m][0], Ah[m][1], Ah[m][2], Ah[m][3], b2, b3);
                MMA16816(Ob, Al[m][0], Al[m][1], Al[m][2], Al[m][3], b2, b3);
                MMA16816(Ob, Ah[m][0], Ah[m][1], Ah[m][2], Ah[m][3], l2, l3);
            }
        }
    }

    // ================= reduce O partials across warps, write p_val ============
    __syncthreads();   // last-stage LDSM reads done before O-red overlays buffers
    {
        float* base = smem + OFF_RED + warp * (32 * REDSTR);
#pragma unroll
        for (int m = 0; m < 2; m++) {
            int r0 = m * 16 + g, r1 = m * 16 + g + 8;
#pragma unroll
            for (int j = 0; j < 8; j++) {
                const float* Oj = O[m * 8 + j];
                *(float2*)(base + r0 * REDSTR + j * 8 + 2 * tg) = make_float2(Oj[0], Oj[1]);
                *(float2*)(base + r1 * REDSTR + j * 8 + 2 * tg) = make_float2(Oj[2], Oj[3]);
            }
        }
    }
    __syncthreads();

#pragma unroll
    for (int it = 0; it < 2; it++) {
        int item = tid + it * 256;       // 0..511
        int row = item >> 4;
        int d0  = (item & 15) * 4;
        float4 acc = make_float4(0.f, 0.f, 0.f, 0.f);
#pragma unroll
        for (int w = 0; w < 8; w++) {
            float4 v = *(const float4*)(smem + OFF_RED + w * (32 * REDSTR) + row * REDSTR + d0);
            acc.x += v.x; acc.y += v.y; acc.z += v.z; acc.w += v.w;
        }
        *(float4*)(p_val + ((size_t)bh * S_LEN + q0 + row) * D_DIM + d0) = acc;
    }
}

extern "C" void kernel_launch(void* const* d_in, const int* in_sizes, int n_in,
                              void* d_out, int out_size)
{
    const float*    Q = (const float*)d_in[0];
    const float*    K = (const float*)d_in[1];
    const float*    V = (const float*)d_in[2];
    const unsigned* M = (const unsigned*)d_in[3];

    float* p_val  = (float*)d_out;
    float* p_attn = (float*)d_out + (size_t)2 * 16 * 2048 * 64;

    const size_t smem_bytes = (size_t)SMEM_WORDS * sizeof(float);  // 157312
    cudaFuncSetAttribute(attn_flash_kernel,
                         cudaFuncAttributeMaxDynamicSharedMemorySize,
                         (int)smem_bytes);

    preconvert_kv<<<dim3(128, NBH), 256>>>(K, V);
    pack_mask<<<512, 256>>>(M);
    attn_flash_kernel<<<dim3(S_LEN / TQ, NBH), 256, smem_bytes>>>(Q, p_val, p_attn);
}

// round 11
// speedup vs baseline: 1.3991x; 1.3991x over previous
#include <cuda_runtime.h>
#include <cuda_fp16.h>
#include <math.h>

#define S_LEN   2048
#define D_DIM   64
#define TQ      32
#define NBH     32
#define KVSTR   36        // u32 words per token row (32 data + 4 pad; LDSM-clean)
#define REDSTR  68

// ---- main-kernel shared memory word offsets ----
#define OFF_Q    0                     // 32*68 = 2176
#define ARR_W    4608                  // 128 tokens * 36 words
#define BUF_W    (2*ARR_W)             // Kh,Vh = 9216 words per buffer
#define OFF_BUF  2176                  // two buffers: 2*9216 = 18432
#define OFF_PART (OFF_BUF + 2*BUF_W)   // 20608 : 32*8
#define OFF_INV  (OFF_PART + 256)      // 20864 : 32
#define SMEM_WORDS (OFF_INV + 32)      // 20896 words = 83584 bytes
#define OFF_RED  OFF_BUF               // O-reduction overlay: 8*32*68 = 17408 <= 18432

// ---- global scratch (single-fp16 K and V, token-row layout) ----
__device__ __align__(16) unsigned g_Kh[(size_t)NBH * S_LEN * KVSTR];
__device__ __align__(16) unsigned g_Vh[(size_t)NBH * S_LEN * KVSTR];
__device__ float    g_inv[(size_t)NBH * S_LEN];
__device__ unsigned g_mpack[(size_t)S_LEN * (S_LEN / 32)];   // 1 bit per mask elem

static __device__ __forceinline__ unsigned cvt_h2(float x, float y) {
    __half2 hh = __floats2half2_rn(x, y);
    return *reinterpret_cast<unsigned*>(&hh);
}
static __device__ __forceinline__ void cvt_hilo2_f16(float x, float y, unsigned &h, unsigned &l) {
    __half2 hh = __floats2half2_rn(x, y);
    float rx = x - __half2float(__low2half(hh));
    float ry = y - __half2float(__high2half(hh));
    __half2 ll = __floats2half2_rn(rx, ry);
    h = *reinterpret_cast<unsigned*>(&hh);
    l = *reinterpret_cast<unsigned*>(&ll);
}

#define MMA16816(C, A0, A1, A2, A3, B0, B1)                                        \
    asm volatile("mma.sync.aligned.m16n8k16.row.col.f32.f16.f16.f32 "              \
                 "{%0,%1,%2,%3},{%4,%5,%6,%7},{%8,%9},{%0,%1,%2,%3};\n"            \
                 : "+f"(C[0]), "+f"(C[1]), "+f"(C[2]), "+f"(C[3])                  \
                 : "r"(A0), "r"(A1), "r"(A2), "r"(A3), "r"(B0), "r"(B1))

#define LDSM_X4(R0, R1, R2, R3, ADDR)                                              \
    asm volatile("ldmatrix.sync.aligned.m8n8.x4.shared.b16 {%0,%1,%2,%3}, [%4];"  \
                 : "=r"(R0), "=r"(R1), "=r"(R2), "=r"(R3) : "r"(ADDR))

#define LDSM_X4_T(R0, R1, R2, R3, ADDR)                                            \
    asm volatile("ldmatrix.sync.aligned.m8n8.x4.trans.shared.b16 {%0,%1,%2,%3}, [%4];" \
                 : "=r"(R0), "=r"(R1), "=r"(R2), "=r"(R3) : "r"(ADDR))

#define CP_ASYNC16(SADDR, GPTR)                                                    \
    asm volatile("cp.async.cg.shared.global [%0], [%1], 16;\n" :: "r"(SADDR), "l"(GPTR))
#define CP_COMMIT()  asm volatile("cp.async.commit_group;\n")
#define CP_WAIT0()   asm volatile("cp.async.wait_group 0;\n" ::: "memory")

// ===================== pre-pass 1: convert K,V -> fp16 scratch ==================
__global__ void __launch_bounds__(256)
preconvert_kv(const float* __restrict__ K, const float* __restrict__ V)
{
    const int bh  = blockIdx.y;
    const int idx = blockIdx.x * 256 + threadIdx.x;
    const int token = idx >> 4, c4 = idx & 15;
    const size_t tok = (size_t)bh * S_LEN + token;
    const size_t go  = tok * KVSTR + c4 * 2;

    float4 k = __ldg((const float4*)(K + tok * D_DIM) + c4);
    *(uint2*)&g_Kh[go] = make_uint2(cvt_h2(k.x, k.y), cvt_h2(k.z, k.w));
    float4 v = __ldg((const float4*)(V + tok * D_DIM) + c4);
    *(uint2*)&g_Vh[go] = make_uint2(cvt_h2(v.x, v.y), cvt_h2(v.z, v.w));
}

// ===================== pre-pass 2: pack mask to 1 bit/elem ======================
__global__ void __launch_bounds__(256)
pack_mask(const unsigned* __restrict__ M)
{
    const int lane = threadIdx.x & 31;
    const int wglob = (blockIdx.x * 256 + threadIdx.x) >> 5;
    const int nwarps = (gridDim.x * 256) >> 5;
    for (int w = wglob; w < S_LEN * (S_LEN / 32); w += nwarps) {
        unsigned bit = (M[(size_t)w * 32 + lane] != 0u) ? 1u : 0u;
        unsigned word = __ballot_sync(0xffffffffu, bit);
        if (lane == 0) g_mpack[w] = word;
    }
}

// ===================== main fused attention kernel ==============================
__global__ void __launch_bounds__(256, 1)
attn_flash_kernel(const float* __restrict__ Q,
                  float* __restrict__ p_val,
                  float* __restrict__ p_attn)
{
    extern __shared__ float smem[];
    const unsigned smem_u32 = (unsigned)__cvta_generic_to_shared(smem);

    const int tid  = threadIdx.x;
    const int warp = tid >> 5;
    const int lane = tid & 31;
    const int g    = lane >> 2;
    const int tg   = lane & 3;
    const int bh   = blockIdx.y;
    const int q0   = blockIdx.x * TQ;
    const int ln0  = warp * 16;

    // ---- ldmatrix per-lane byte addresses (buffer 0) ----
    const int qk_row  = ln0 + ((lane >> 4) << 3) + (lane & 7);
    const unsigned qk_off = (unsigned)(qk_row * KVSTR + (((lane >> 3) & 1) << 2)) * 4u;
    const unsigned kh_base = smem_u32 + (OFF_BUF + 0 * ARR_W) * 4u + qk_off;
    const int pv_row  = ln0 + (((lane >> 3) & 1) << 3) + (lane & 7);
    const unsigned pv_off = (unsigned)(pv_row * KVSTR + ((lane >> 4) << 2)) * 4u;
    const unsigned vh_base = smem_u32 + (OFF_BUF + 1 * ARR_W) * 4u + pv_off;

    // ================= Q tile (32 rows) -> smem -> A fragments (hi/lo fp16) ====
    {
#pragma unroll
        for (int i = 0; i < 2; i++) {
            int idx = tid + i * 256;
            int row = idx >> 4, c4 = idx & 15;
            float4 qv = __ldg((const float4*)(Q + ((size_t)bh * S_LEN + q0 + row) * D_DIM) + c4);
            *((float4*)(smem + OFF_Q + row * 68 + c4 * 4)) = qv;
        }
    }
    __syncthreads();

    unsigned qah[2][4][4], qal[2][4][4];
#pragma unroll
    for (int m = 0; m < 2; m++) {
        int r0 = m * 16 + g, r1 = m * 16 + g + 8;
#pragma unroll
        for (int ks = 0; ks < 4; ks++) {
            int c = ks * 16 + tg * 2;
            float2 x0 = *(const float2*)(smem + OFF_Q + r0 * 68 + c);
            float2 x1 = *(const float2*)(smem + OFF_Q + r1 * 68 + c);
            float2 x2 = *(const float2*)(smem + OFF_Q + r0 * 68 + c + 8);
            float2 x3 = *(const float2*)(smem + OFF_Q + r1 * 68 + c + 8);
            cvt_hilo2_f16(x0.x, x0.y, qah[m][ks][0], qal[m][ks][0]);
            cvt_hilo2_f16(x1.x, x1.y, qah[m][ks][1], qal[m][ks][1]);
            cvt_hilo2_f16(x2.x, x2.y, qah[m][ks][2], qal[m][ks][2]);
            cvt_hilo2_f16(x3.x, x3.y, qah[m][ks][3], qal[m][ks][3]);
        }
    }

    float rs[4] = {0.f, 0.f, 0.f, 0.f};
    float O[16][4];
#pragma unroll
    for (int j = 0; j < 16; j++) { O[j][0] = O[j][1] = O[j][2] = O[j][3] = 0.f; }

    // mask word pointers (one broadcast word per row per stage) and p_attn rows
    const unsigned* mp[4];
    float* pa[4];
#pragma unroll
    for (int r = 0; r < 4; r++) {
        int row = (r >> 1) * 16 + g + (r & 1) * 8;    // g, g+8, 16+g, 24+g
        mp[r] = g_mpack + (size_t)(q0 + row) * 64 + (warp >> 1);
        pa[r] = p_attn + ((size_t)bh * S_LEN + q0 + row) * S_LEN;
    }
    const unsigned posbase = (warp & 1) * 16;
    const size_t bh_base = (size_t)bh * S_LEN * KVSTR;

    // ---- prologue: issue stage 0 loads (Kh + Vh) ----
    {
        for (int i = tid; i < ARR_W / 4; i += 256) {
            unsigned so = (unsigned)(OFF_BUF * 4 + i * 16);
            CP_ASYNC16(smem_u32 + so,             (const uint4*)(g_Kh + bh_base) + i);
            CP_ASYNC16(smem_u32 + so + ARR_W * 4, (const uint4*)(g_Vh + bh_base) + i);
        }
        CP_COMMIT();
    }

    // =================== pipelined main loop: 16 stages of 128 tokens ==========
    for (int st = 0; st < 16; st++) {
        const int kb0 = st * 128;
        const unsigned bufoff = (unsigned)(st & 1) * (BUF_W * 4);

        CP_WAIT0();
        __syncthreads();   // stage-st data visible; prev compute done

        // ---- prefetch stage st+1 into the other buffer ----
        if (st < 15) {
            const size_t sb = bh_base + (size_t)(kb0 + 128) * KVSTR;
            const unsigned dst = (unsigned)(OFF_BUF * 4) + (unsigned)((st + 1) & 1) * (BUF_W * 4);
            for (int i = tid; i < ARR_W / 4; i += 256) {
                unsigned so = dst + (unsigned)i * 16u;
                CP_ASYNC16(smem_u32 + so,             (const uint4*)(g_Kh + sb) + i);
                CP_ASYNC16(smem_u32 + so + ARR_W * 4, (const uint4*)(g_Vh + sb) + i);
            }
            CP_COMMIT();
        }

        // ---- QK^T: 2 M-tiles x warp's 16 tokens, 2-term (Qh + Ql)·Kh ----
        float C00[4] = {0,0,0,0}, C01[4] = {0,0,0,0};
        float C10[4] = {0,0,0,0}, C11[4] = {0,0,0,0};
#pragma unroll
        for (int ks = 0; ks < 4; ks++) {
            unsigned b0, b1, b2, b3;
            LDSM_X4(b0, b1, b2, b3, kh_base + bufoff + ks * 32u);
            MMA16816(C00, qah[0][ks][0], qah[0][ks][1], qah[0][ks][2], qah[0][ks][3], b0, b1);
            MMA16816(C01, qah[0][ks][0], qah[0][ks][1], qah[0][ks][2], qah[0][ks][3], b2, b3);
            MMA16816(C10, qah[1][ks][0], qah[1][ks][1], qah[1][ks][2], qah[1][ks][3], b0, b1);
            MMA16816(C11, qah[1][ks][0], qah[1][ks][1], qah[1][ks][2], qah[1][ks][3], b2, b3);
            MMA16816(C00, qal[0][ks][0], qal[0][ks][1], qal[0][ks][2], qal[0][ks][3], b0, b1);
            MMA16816(C01, qal[0][ks][0], qal[0][ks][1], qal[0][ks][2], qal[0][ks][3], b2, b3);
            MMA16816(C10, qal[1][ks][0], qal[1][ks][1], qal[1][ks][2], qal[1][ks][3], b0, b1);
            MMA16816(C11, qal[1][ks][0], qal[1][ks][1], qal[1][ks][2], qal[1][ks][3], b2, b3);
        }

        // ---- epilogue: mask(bit), exp, rowsum; unnormalized exp -> p_attn ----
        unsigned mw0 = __ldg(mp[0] + st * 4);
        unsigned mw1 = __ldg(mp[1] + st * 4);
        unsigned mw2 = __ldg(mp[2] + st * 4);
        unsigned mw3 = __ldg(mp[3] + st * 4);
        float e[2][2][4];
#pragma unroll
        for (int m = 0; m < 2; m++) {
            unsigned ma = m ? mw2 : mw0;   // row m*16+g
            unsigned mb = m ? mw3 : mw1;   // row m*16+g+8
#pragma unroll
            for (int t = 0; t < 2; t++) {
                const float* C = m ? (t ? C11 : C10) : (t ? C01 : C00);
                int nb = kb0 + ln0 + t * 8 + tg * 2;
                unsigned sh = posbase + t * 8 + tg * 2;
                float* E = e[m][t];
                E[0] = ((ma >> sh) & 1u)       ? 0.f : __expf(C[0] * 0.125f);
                E[1] = ((ma >> (sh + 1)) & 1u) ? 0.f : __expf(C[1] * 0.125f);
                E[2] = ((mb >> sh) & 1u)       ? 0.f : __expf(C[2] * 0.125f);
                E[3] = ((mb >> (sh + 1)) & 1u) ? 0.f : __expf(C[3] * 0.125f);
                rs[2 * m]     += E[0] + E[1];
                rs[2 * m + 1] += E[2] + E[3];
                __stcs((float2*)(pa[2 * m]     + nb), make_float2(E[0], E[1]));
                __stcs((float2*)(pa[2 * m + 1] + nb), make_float2(E[2], E[3]));
            }
        }

        // ---- E -> A-frag hi/lo fp16 (C-frag layout == A-frag layout) ----
        unsigned Ah[2][4], Al[2][4];
#pragma unroll
        for (int m = 0; m < 2; m++) {
            cvt_hilo2_f16(e[m][0][0], e[m][0][1], Ah[m][0], Al[m][0]);
            cvt_hilo2_f16(e[m][0][2], e[m][0][3], Ah[m][1], Al[m][1]);
            cvt_hilo2_f16(e[m][1][0], e[m][1][1], Ah[m][2], Al[m][2]);
            cvt_hilo2_f16(e[m][1][2], e[m][1][3], Ah[m][3], Al[m][3]);
        }

        // ---- PV: warp's 16 tokens x all 64 d, 2-term (Ph + Pl)·Vh ----
#pragma unroll
        for (int jp = 0; jp < 4; jp++) {
            unsigned b0, b1, b2, b3;
            LDSM_X4_T(b0, b1, b2, b3, vh_base + bufoff + jp * 32u);
#pragma unroll
            for (int m = 0; m < 2; m++) {
                float* Oa = O[m * 8 + 2 * jp];
                float* Ob = O[m * 8 + 2 * jp + 1];
                MMA16816(Oa, Ah[m][0], Ah[m][1], Ah[m][2], Ah[m][3], b0, b1);
                MMA16816(Oa, Al[m][0], Al[m][1], Al[m][2], Al[m][3], b0, b1);
                MMA16816(Ob, Ah[m][0], Ah[m][1], Ah[m][2], Ah[m][3], b2, b3);
                MMA16816(Ob, Al[m][0], Al[m][1], Al[m][2], Al[m][3], b2, b3);
            }
        }
    }

    // ================= rowsums ================================================
#pragma unroll
    for (int r = 0; r < 4; r++) {
        rs[r] += __shfl_xor_sync(0xffffffff, rs[r], 1);
        rs[r] += __shfl_xor_sync(0xffffffff, rs[r], 2);
    }

    __syncthreads();   // last-stage LDSM reads done before O-red overlays buffers

    if (tg == 0) {
#pragma unroll
        for (int r = 0; r < 4; r++) {
            int row = (r >> 1) * 16 + g + (r & 1) * 8;
            smem[OFF_PART + row * 8 + warp] = rs[r];
        }
    }
    {
        float* base = smem + OFF_RED + warp * (32 * REDSTR);
#pragma unroll
        for (int m = 0; m < 2; m++) {
            int r0 = m * 16 + g, r1 = m * 16 + g + 8;
#pragma unroll
            for (int j = 0; j < 8; j++) {
                const float* Oj = O[m * 8 + j];
                *(float2*)(base + r0 * REDSTR + j * 8 + 2 * tg) = make_float2(Oj[0], Oj[1]);
                *(float2*)(base + r1 * REDSTR + j * 8 + 2 * tg) = make_float2(Oj[2], Oj[3]);
            }
        }
    }
    __syncthreads();

    if (tid < TQ) {
        float s = 0.f;
#pragma unroll
        for (int i = 0; i < 8; i++) s += smem[OFF_PART + tid * 8 + i];
        float iv = 1.0f / s;
        smem[OFF_INV + tid] = iv;
        g_inv[(size_t)bh * S_LEN + q0 + tid] = iv;
    }
    __syncthreads();

    // ================= reduce O partials, write p_val =========================
#pragma unroll
    for (int it = 0; it < 2; it++) {
        int item = tid + it * 256;       // 0..511
        int row = item >> 4;
        int d0  = (item & 15) * 4;
        float4 acc = make_float4(0.f, 0.f, 0.f, 0.f);
#pragma unroll
        for (int w = 0; w < 8; w++) {
            float4 v = *(const float4*)(smem + OFF_RED + w * (32 * REDSTR) + row * REDSTR + d0);
            acc.x += v.x; acc.y += v.y; acc.z += v.z; acc.w += v.w;
        }
        float inv = smem[OFF_INV + row];
        acc.x *= inv; acc.y *= inv; acc.z *= inv; acc.w *= inv;
        *(float4*)(p_val + ((size_t)bh * S_LEN + q0 + row) * D_DIM + d0) = acc;
    }
}

// ===================== normalize pass: p_attn *= inv[row] =======================
__global__ void __launch_bounds__(256)
normalize_pattn(float* __restrict__ p_attn)
{
    float4* p4 = (float4*)p_attn;
    const size_t stride = (size_t)gridDim.x * 256;
    size_t i4 = (size_t)blockIdx.x * 256 + threadIdx.x;
#pragma unroll
    for (int it = 0; it < 8; it++) {
        unsigned row = (unsigned)(i4 >> 9);
        float inv = __ldg(&g_inv[row]);
        float4 v = p4[i4];
        v.x *= inv; v.y *= inv; v.z *= inv; v.w *= inv;
        p4[i4] = v;
        i4 += stride;
    }
}

extern "C" void kernel_launch(void* const* d_in, const int* in_sizes, int n_in,
                              void* d_out, int out_size)
{
    const float*    Q = (const float*)d_in[0];
    const float*    K = (const float*)d_in[1];
    const float*    V = (const float*)d_in[2];
    const unsigned* M = (const unsigned*)d_in[3];

    float* p_val  = (float*)d_out;
    float* p_attn = (float*)d_out + (size_t)2 * 16 * 2048 * 64;

    const size_t smem_bytes = (size_t)SMEM_WORDS * sizeof(float);  // 83584
    cudaFuncSetAttribute(attn_flash_kernel,
                         cudaFuncAttributeMaxDynamicSharedMemorySize,
                         (int)smem_bytes);

    preconvert_kv<<<dim3(128, NBH), 256>>>(K, V);
    pack_mask<<<512, 256>>>(M);
    attn_flash_kernel<<<dim3(S_LEN / TQ, NBH), 256, smem_bytes>>>(Q, p_val, p_attn);
    normalize_pattn<<<16384, 256>>>(p_attn);
}

// round 12
// speedup vs baseline: 1.5451x; 1.1044x over previous
#include <cuda_runtime.h>
#include <cuda_fp16.h>
#include <math.h>

#define S_LEN   2048
#define D_DIM   64
#define TQ      16
#define NBH     32
#define KVSTR   36        // u32 words per token row (32 data + 4 pad; LDSM-clean)
#define SSTRIDE 2056      // fp32 words per Stile row (mod 32 = 8; 514 f4 -> clean)
#define REDSTR  68

// ---- main-kernel shared memory word offsets ----
#define OFF_S    0                     // Stile: 16*2056 = 32896
#define OFF_Q    32896                 // 16*68 = 1088
#define ARR_W    4608                  // 128 tokens * 36 words
#define BUF_W    (2*ARR_W)             // Kh,Vh = 9216 words per buffer
#define OFF_BUF  33984                 // two buffers: 2*9216 = 18432
#define OFF_PART (OFF_BUF + 2*BUF_W)   // 52416 : 16*8
#define OFF_INV  (OFF_PART + 128)      // 52544 : 16
#define SMEM_WORDS (OFF_INV + 16)      // 52560 words = 210240 bytes
#define OFF_RED  OFF_BUF               // O-reduction overlay: 8*16*68 = 8704 <= 18432

// ---- global scratch (single-fp16 K and V, token-row layout) ----
__device__ __align__(16) unsigned g_Kh[(size_t)NBH * S_LEN * KVSTR];
__device__ __align__(16) unsigned g_Vh[(size_t)NBH * S_LEN * KVSTR];
__device__ unsigned g_mpack[(size_t)S_LEN * (S_LEN / 32)];   // 1 bit per mask elem

static __device__ __forceinline__ unsigned cvt_h2(float x, float y) {
    __half2 hh = __floats2half2_rn(x, y);
    return *reinterpret_cast<unsigned*>(&hh);
}
static __device__ __forceinline__ void cvt_hilo2_f16(float x, float y, unsigned &h, unsigned &l) {
    __half2 hh = __floats2half2_rn(x, y);
    float rx = x - __half2float(__low2half(hh));
    float ry = y - __half2float(__high2half(hh));
    __half2 ll = __floats2half2_rn(rx, ry);
    h = *reinterpret_cast<unsigned*>(&hh);
    l = *reinterpret_cast<unsigned*>(&ll);
}

#define MMA16816(C, A0, A1, A2, A3, B0, B1)                                        \
    asm volatile("mma.sync.aligned.m16n8k16.row.col.f32.f16.f16.f32 "              \
                 "{%0,%1,%2,%3},{%4,%5,%6,%7},{%8,%9},{%0,%1,%2,%3};\n"            \
                 : "+f"(C[0]), "+f"(C[1]), "+f"(C[2]), "+f"(C[3])                  \
                 : "r"(A0), "r"(A1), "r"(A2), "r"(A3), "r"(B0), "r"(B1))

#define LDSM_X4(R0, R1, R2, R3, ADDR)                                              \
    asm volatile("ldmatrix.sync.aligned.m8n8.x4.shared.b16 {%0,%1,%2,%3}, [%4];"  \
                 : "=r"(R0), "=r"(R1), "=r"(R2), "=r"(R3) : "r"(ADDR))

#define LDSM_X4_T(R0, R1, R2, R3, ADDR)                                            \
    asm volatile("ldmatrix.sync.aligned.m8n8.x4.trans.shared.b16 {%0,%1,%2,%3}, [%4];" \
                 : "=r"(R0), "=r"(R1), "=r"(R2), "=r"(R3) : "r"(ADDR))

#define CP_ASYNC16(SADDR, GPTR)                                                    \
    asm volatile("cp.async.cg.shared.global [%0], [%1], 16;\n" :: "r"(SADDR), "l"(GPTR))
#define CP_COMMIT()  asm volatile("cp.async.commit_group;\n")
#define CP_WAIT0()   asm volatile("cp.async.wait_group 0;\n" ::: "memory")

// ===================== pre-pass 1: convert K,V -> fp16 scratch ==================
__global__ void __launch_bounds__(256)
preconvert_kv(const float* __restrict__ K, const float* __restrict__ V)
{
    const int bh  = blockIdx.y;
    const int idx = blockIdx.x * 256 + threadIdx.x;
    const int token = idx >> 4, c4 = idx & 15;
    const size_t tok = (size_t)bh * S_LEN + token;
    const size_t go  = tok * KVSTR + c4 * 2;

    float4 k = __ldg((const float4*)(K + tok * D_DIM) + c4);
    *(uint2*)&g_Kh[go] = make_uint2(cvt_h2(k.x, k.y), cvt_h2(k.z, k.w));
    float4 v = __ldg((const float4*)(V + tok * D_DIM) + c4);
    *(uint2*)&g_Vh[go] = make_uint2(cvt_h2(v.x, v.y), cvt_h2(v.z, v.w));
}

// ===================== pre-pass 2: pack mask to 1 bit/elem ======================
__global__ void __launch_bounds__(256)
pack_mask(const unsigned* __restrict__ M)
{
    const int lane = threadIdx.x & 31;
    const int wglob = (blockIdx.x * 256 + threadIdx.x) >> 5;
    const int nwarps = (gridDim.x * 256) >> 5;
    for (int w = wglob; w < S_LEN * (S_LEN / 32); w += nwarps) {
        unsigned bit = (M[(size_t)w * 32 + lane] != 0u) ? 1u : 0u;
        unsigned word = __ballot_sync(0xffffffffu, bit);
        if (lane == 0) g_mpack[w] = word;
    }
}

// ===================== main fused attention kernel ==============================
__global__ void __launch_bounds__(256, 1)
attn_flash_kernel(const float* __restrict__ Q,
                  float* __restrict__ p_val,
                  float* __restrict__ p_attn)
{
    extern __shared__ float smem[];
    const unsigned smem_u32 = (unsigned)__cvta_generic_to_shared(smem);

    const int tid  = threadIdx.x;
    const int warp = tid >> 5;
    const int lane = tid & 31;
    const int g    = lane >> 2;
    const int tg   = lane & 3;
    const int bh   = blockIdx.y;
    const int q0   = blockIdx.x * TQ;
    const int ln0  = warp * 16;

    // ---- ldmatrix per-lane byte addresses (buffer 0) ----
    const int qk_row  = ln0 + ((lane >> 4) << 3) + (lane & 7);
    const unsigned qk_off = (unsigned)(qk_row * KVSTR + (((lane >> 3) & 1) << 2)) * 4u;
    const unsigned kh_base = smem_u32 + OFF_BUF * 4u + qk_off;
    const int pv_row  = ln0 + (((lane >> 3) & 1) << 3) + (lane & 7);
    const unsigned pv_off = (unsigned)(pv_row * KVSTR + ((lane >> 4) << 2)) * 4u;
    const unsigned vh_base = smem_u32 + (OFF_BUF + ARR_W) * 4u + pv_off;

    // ================= Q tile (16 rows) -> smem -> A fragments (hi/lo fp16) ====
    {
        int row = tid >> 4, c4 = tid & 15;
        float4 qv = __ldg((const float4*)(Q + ((size_t)bh * S_LEN + q0 + row) * D_DIM) + c4);
        *((float4*)(smem + OFF_Q + row * 68 + c4 * 4)) = qv;
    }
    __syncthreads();

    unsigned qah[4][4], qal[4][4];
#pragma unroll
    for (int ks = 0; ks < 4; ks++) {
        int c = ks * 16 + tg * 2;
        float2 x0 = *(const float2*)(smem + OFF_Q + g * 68 + c);
        float2 x1 = *(const float2*)(smem + OFF_Q + (g + 8) * 68 + c);
        float2 x2 = *(const float2*)(smem + OFF_Q + g * 68 + c + 8);
        float2 x3 = *(const float2*)(smem + OFF_Q + (g + 8) * 68 + c + 8);
        cvt_hilo2_f16(x0.x, x0.y, qah[ks][0], qal[ks][0]);
        cvt_hilo2_f16(x1.x, x1.y, qah[ks][1], qal[ks][1]);
        cvt_hilo2_f16(x2.x, x2.y, qah[ks][2], qal[ks][2]);
        cvt_hilo2_f16(x3.x, x3.y, qah[ks][3], qal[ks][3]);
    }

    float rs0 = 0.f, rs1 = 0.f;
    float O[8][4];
#pragma unroll
    for (int j = 0; j < 8; j++) { O[j][0] = O[j][1] = O[j][2] = O[j][3] = 0.f; }

    // mask word pointers: rows q0+g and q0+g+8; warp's 16 tokens -> word warp>>1
    const unsigned* mp0 = g_mpack + (size_t)(q0 + g) * 64 + (warp >> 1);
    const unsigned* mp1 = g_mpack + (size_t)(q0 + g + 8) * 64 + (warp >> 1);
    const unsigned posbase = (warp & 1) * 16;
    const size_t bh_base = (size_t)bh * S_LEN * KVSTR;

    // ---- prologue: issue stage 0 loads (Kh + Vh) ----
    {
        for (int i = tid; i < ARR_W / 4; i += 256) {
            unsigned so = (unsigned)(OFF_BUF * 4 + i * 16);
            CP_ASYNC16(smem_u32 + so,             (const uint4*)(g_Kh + bh_base) + i);
            CP_ASYNC16(smem_u32 + so + ARR_W * 4, (const uint4*)(g_Vh + bh_base) + i);
        }
        CP_COMMIT();
    }

    // =================== pipelined main loop: 16 stages of 128 tokens ==========
    for (int st = 0; st < 16; st++) {
        const int kb0 = st * 128;
        const unsigned bufoff = (unsigned)(st & 1) * (BUF_W * 4);

        CP_WAIT0();
        __syncthreads();

        // ---- prefetch stage st+1 into the other buffer ----
        if (st < 15) {
            const size_t sbg = bh_base + (size_t)(kb0 + 128) * KVSTR;
            const unsigned dst = (unsigned)(OFF_BUF * 4) + (unsigned)((st + 1) & 1) * (BUF_W * 4);
            for (int i = tid; i < ARR_W / 4; i += 256) {
                unsigned so = dst + (unsigned)i * 16u;
                CP_ASYNC16(smem_u32 + so,             (const uint4*)(g_Kh + sbg) + i);
                CP_ASYNC16(smem_u32 + so + ARR_W * 4, (const uint4*)(g_Vh + sbg) + i);
            }
            CP_COMMIT();
        }

        // ---- QK^T: warp's 16 tokens (two n-tiles), 2-term (Qh + Ql)·Kh ----
        float C0[4] = {0,0,0,0}, C1[4] = {0,0,0,0};
#pragma unroll
        for (int ks = 0; ks < 4; ks++) {
            unsigned b0, b1, b2, b3;
            LDSM_X4(b0, b1, b2, b3, kh_base + bufoff + ks * 32u);
            MMA16816(C0, qah[ks][0], qah[ks][1], qah[ks][2], qah[ks][3], b0, b1);
            MMA16816(C1, qah[ks][0], qah[ks][1], qah[ks][2], qah[ks][3], b2, b3);
            MMA16816(C0, qal[ks][0], qal[ks][1], qal[ks][2], qal[ks][3], b0, b1);
            MMA16816(C1, qal[ks][0], qal[ks][1], qal[ks][2], qal[ks][3], b2, b3);
        }

        // ---- epilogue: mask(bit), exp, rowsum; e -> Stile (smem) ----
        unsigned mw0 = __ldg(mp0 + st * 4);
        unsigned mw1 = __ldg(mp1 + st * 4);
        float e[2][4];
#pragma unroll
        for (int t = 0; t < 2; t++) {
            const float* C = t ? C1 : C0;
            int nb = kb0 + ln0 + t * 8 + tg * 2;
            unsigned sh = posbase + t * 8 + tg * 2;
            float* E = e[t];
            E[0] = ((mw0 >> sh) & 1u)       ? 0.f : __expf(C[0] * 0.125f);
            E[1] = ((mw0 >> (sh + 1)) & 1u) ? 0.f : __expf(C[1] * 0.125f);
            E[2] = ((mw1 >> sh) & 1u)       ? 0.f : __expf(C[2] * 0.125f);
            E[3] = ((mw1 >> (sh + 1)) & 1u) ? 0.f : __expf(C[3] * 0.125f);
            rs0 += E[0] + E[1];
            rs1 += E[2] + E[3];
            *(float2*)(smem + OFF_S + g * SSTRIDE + nb)       = make_float2(E[0], E[1]);
            *(float2*)(smem + OFF_S + (g + 8) * SSTRIDE + nb) = make_float2(E[2], E[3]);
        }

        // ---- E -> A-frag fp16 (1-term PV) ----
        unsigned Ah[4];
        Ah[0] = cvt_h2(e[0][0], e[0][1]);
        Ah[1] = cvt_h2(e[0][2], e[0][3]);
        Ah[2] = cvt_h2(e[1][0], e[1][1]);
        Ah[3] = cvt_h2(e[1][2], e[1][3]);

        // ---- PV: warp's 16 tokens x all 64 d, 1-term Ph·Vh ----
#pragma unroll
        for (int jp = 0; jp < 4; jp++) {
            unsigned b0, b1, b2, b3;
            LDSM_X4_T(b0, b1, b2, b3, vh_base + bufoff + jp * 32u);
            MMA16816(O[2*jp],     Ah[0], Ah[1], Ah[2], Ah[3], b0, b1);
            MMA16816(O[2*jp + 1], Ah[0], Ah[1], Ah[2], Ah[3], b2, b3);
        }
    }

    // ================= rowsums ================================================
    rs0 += __shfl_xor_sync(0xffffffff, rs0, 1);
    rs0 += __shfl_xor_sync(0xffffffff, rs0, 2);
    rs1 += __shfl_xor_sync(0xffffffff, rs1, 1);
    rs1 += __shfl_xor_sync(0xffffffff, rs1, 2);

    __syncthreads();   // last-stage LDSM reads done before O-red overlays buffers

    if (tg == 0) {
        smem[OFF_PART + g * 8 + warp]       = rs0;
        smem[OFF_PART + (g + 8) * 8 + warp] = rs1;
    }
    {
        float* base = smem + OFF_RED + warp * (16 * REDSTR);
#pragma unroll
        for (int j = 0; j < 8; j++) {
            *(float2*)(base + g * REDSTR + j * 8 + 2 * tg)       = make_float2(O[j][0], O[j][1]);
            *(float2*)(base + (g + 8) * REDSTR + j * 8 + 2 * tg) = make_float2(O[j][2], O[j][3]);
        }
    }
    __syncthreads();

    if (tid < TQ) {
        float s = 0.f;
#pragma unroll
        for (int i = 0; i < 8; i++) s += smem[OFF_PART + tid * 8 + i];
        smem[OFF_INV + tid] = 1.0f / s;
    }
    __syncthreads();

    // ================= reduce O partials, write p_val =========================
    {
        int row = tid >> 4;
        int d0  = (tid & 15) * 4;
        float4 acc = make_float4(0.f, 0.f, 0.f, 0.f);
#pragma unroll
        for (int w = 0; w < 8; w++) {
            float4 v = *(const float4*)(smem + OFF_RED + w * (16 * REDSTR) + row * REDSTR + d0);
            acc.x += v.x; acc.y += v.y; acc.z += v.z; acc.w += v.w;
        }
        float inv = smem[OFF_INV + row];
        acc.x *= inv; acc.y *= inv; acc.z *= inv; acc.w *= inv;
        *(float4*)(p_val + ((size_t)bh * S_LEN + q0 + row) * D_DIM + d0) = acc;
    }

    // ================= write normalized p_attn from Stile =====================
    {
        float* out = p_attn + ((size_t)bh * S_LEN + q0) * S_LEN;
        const float4* Sf4 = (const float4*)(smem + OFF_S);
#pragma unroll
        for (int i = 0; i < 32; i++) {
            int idx  = tid + i * 256;
            int row  = idx >> 9;           // 512 float4 per S-row
            int col4 = idx & 511;
            float4 v = Sf4[row * (SSTRIDE / 4) + col4];
            float inv = smem[OFF_INV + row];
            v.x *= inv; v.y *= inv; v.z *= inv; v.w *= inv;
            __stcs((float4*)(out + (size_t)row * S_LEN) + col4, v);
        }
    }
}

extern "C" void kernel_launch(void* const* d_in, const int* in_sizes, int n_in,
                              void* d_out, int out_size)
{
    const float*    Q = (const float*)d_in[0];
    const float*    K = (const float*)d_in[1];
    const float*    V = (const float*)d_in[2];
    const unsigned* M = (const unsigned*)d_in[3];

    float* p_val  = (float*)d_out;
    float* p_attn = (float*)d_out + (size_t)2 * 16 * 2048 * 64;

    const size_t smem_bytes = (size_t)SMEM_WORDS * sizeof(float);  // 210240
    cudaFuncSetAttribute(attn_flash_kernel,
                         cudaFuncAttributeMaxDynamicSharedMemorySize,
                         (int)smem_bytes);

    preconvert_kv<<<dim3(128, NBH), 256>>>(K, V);
    pack_mask<<<512, 256>>>(M);
    attn_flash_kernel<<<dim3(S_LEN / TQ, NBH), 256, smem_bytes>>>(Q, p_val, p_attn);
}

// round 13
// speedup vs baseline: 1.7154x; 1.1102x over previous
#include <cuda_runtime.h>
#include <cuda_fp16.h>
#include <math.h>

#define S_LEN   2048
#define D_DIM   64
#define TQ      32
#define NBH     32
#define KVSTR   36        // u32 words per token row (32 data + 4 pad; LDSM-clean)
#define REDSTR  68

// ---- main-kernel shared memory word offsets ----
#define OFF_Q    0                     // 32*68 = 2176
#define ARR_W    4608                  // 128 tokens * 36 words
#define BUF_W    (2*ARR_W)             // Kh,Vh = 9216 words per buffer
#define OFF_BUF  2176                  // two buffers: 2*9216 = 18432
#define OFF_PART (OFF_BUF + 2*BUF_W)   // 20608 : 32*8
#define OFF_INV  (OFF_PART + 256)      // 20864 : 32
#define SMEM_WORDS (OFF_INV + 32)      // 20896 words = 83584 bytes
#define OFF_RED  OFF_BUF               // O-reduction overlay: 8*32*68 = 17408 <= 18432

// ---- global scratch (single-fp16 K and V, token-row layout) ----
__device__ __align__(16) unsigned g_Kh[(size_t)NBH * S_LEN * KVSTR];
__device__ __align__(16) unsigned g_Vh[(size_t)NBH * S_LEN * KVSTR];
__device__ unsigned g_mpack[(size_t)S_LEN * (S_LEN / 32)];   // 1 bit per mask elem

static __device__ __forceinline__ unsigned cvt_h2(float x, float y) {
    __half2 hh = __floats2half2_rn(x, y);
    return *reinterpret_cast<unsigned*>(&hh);
}
static __device__ __forceinline__ void cvt_hilo2_f16(float x, float y, unsigned &h, unsigned &l) {
    __half2 hh = __floats2half2_rn(x, y);
    float rx = x - __half2float(__low2half(hh));
    float ry = y - __half2float(__high2half(hh));
    __half2 ll = __floats2half2_rn(rx, ry);
    h = *reinterpret_cast<unsigned*>(&hh);
    l = *reinterpret_cast<unsigned*>(&ll);
}

#define MMA16816(C, A0, A1, A2, A3, B0, B1)                                        \
    asm volatile("mma.sync.aligned.m16n8k16.row.col.f32.f16.f16.f32 "              \
                 "{%0,%1,%2,%3},{%4,%5,%6,%7},{%8,%9},{%0,%1,%2,%3};\n"            \
                 : "+f"(C[0]), "+f"(C[1]), "+f"(C[2]), "+f"(C[3])                  \
                 : "r"(A0), "r"(A1), "r"(A2), "r"(A3), "r"(B0), "r"(B1))

#define LDSM_X4(R0, R1, R2, R3, ADDR)                                              \
    asm volatile("ldmatrix.sync.aligned.m8n8.x4.shared.b16 {%0,%1,%2,%3}, [%4];"  \
                 : "=r"(R0), "=r"(R1), "=r"(R2), "=r"(R3) : "r"(ADDR))

#define LDSM_X4_T(R0, R1, R2, R3, ADDR)                                            \
    asm volatile("ldmatrix.sync.aligned.m8n8.x4.trans.shared.b16 {%0,%1,%2,%3}, [%4];" \
                 : "=r"(R0), "=r"(R1), "=r"(R2), "=r"(R3) : "r"(ADDR))

#define CP_ASYNC16(SADDR, GPTR)                                                    \
    asm volatile("cp.async.cg.shared.global [%0], [%1], 16;\n" :: "r"(SADDR), "l"(GPTR))
#define CP_COMMIT()  asm volatile("cp.async.commit_group;\n")
#define CP_WAIT0()   asm volatile("cp.async.wait_group 0;\n" ::: "memory")

// ===================== pre-pass 1: convert K,V -> fp16 scratch ==================
__global__ void __launch_bounds__(256)
preconvert_kv(const float* __restrict__ K, const float* __restrict__ V)
{
    const int bh  = blockIdx.y;
    const int idx = blockIdx.x * 256 + threadIdx.x;
    const int token = idx >> 4, c4 = idx & 15;
    const size_t tok = (size_t)bh * S_LEN + token;
    const size_t go  = tok * KVSTR + c4 * 2;

    float4 k = __ldg((const float4*)(K + tok * D_DIM) + c4);
    *(uint2*)&g_Kh[go] = make_uint2(cvt_h2(k.x, k.y), cvt_h2(k.z, k.w));
    float4 v = __ldg((const float4*)(V + tok * D_DIM) + c4);
    *(uint2*)&g_Vh[go] = make_uint2(cvt_h2(v.x, v.y), cvt_h2(v.z, v.w));
}

// ===================== pre-pass 2: pack mask to 1 bit/elem ======================
__global__ void __launch_bounds__(256)
pack_mask(const unsigned* __restrict__ M)
{
    const int lane = threadIdx.x & 31;
    const int wglob = (blockIdx.x * 256 + threadIdx.x) >> 5;
    const int nwarps = (gridDim.x * 256) >> 5;
    for (int w = wglob; w < S_LEN * (S_LEN / 32); w += nwarps) {
        unsigned bit = (M[(size_t)w * 32 + lane] != 0u) ? 1u : 0u;
        unsigned word = __ballot_sync(0xffffffffu, bit);
        if (lane == 0) g_mpack[w] = word;
    }
}

// ===================== main fused attention kernel ==============================
__global__ void __launch_bounds__(256, 1)
attn_flash_kernel(const float* __restrict__ Q,
                  float* __restrict__ p_val,
                  float* __restrict__ p_attn)
{
    extern __shared__ float smem[];
    const unsigned smem_u32 = (unsigned)__cvta_generic_to_shared(smem);

    const int tid  = threadIdx.x;
    const int warp = tid >> 5;
    const int lane = tid & 31;
    const int g    = lane >> 2;
    const int tg   = lane & 3;
    const int bh   = blockIdx.y;
    const int q0   = blockIdx.x * TQ;
    const int ln0  = warp * 16;

    // ---- ldmatrix per-lane byte addresses (buffer 0) ----
    const int qk_row  = ln0 + ((lane >> 4) << 3) + (lane & 7);
    const unsigned qk_off = (unsigned)(qk_row * KVSTR + (((lane >> 3) & 1) << 2)) * 4u;
    const unsigned kh_base = smem_u32 + OFF_BUF * 4u + qk_off;
    const int pv_row  = ln0 + (((lane >> 3) & 1) << 3) + (lane & 7);
    const unsigned pv_off = (unsigned)(pv_row * KVSTR + ((lane >> 4) << 2)) * 4u;
    const unsigned vh_base = smem_u32 + (OFF_BUF + ARR_W) * 4u + pv_off;

    // ================= Q tile (32 rows) -> smem -> A fragments (hi/lo fp16) ====
    {
#pragma unroll
        for (int i = 0; i < 2; i++) {
            int idx = tid + i * 256;
            int row = idx >> 4, c4 = idx & 15;
            float4 qv = __ldg((const float4*)(Q + ((size_t)bh * S_LEN + q0 + row) * D_DIM) + c4);
            *((float4*)(smem + OFF_Q + row * 68 + c4 * 4)) = qv;
        }
    }
    __syncthreads();

    unsigned qah[2][4][4], qal[2][4][4];
#pragma unroll
    for (int m = 0; m < 2; m++) {
        int r0 = m * 16 + g, r1 = m * 16 + g + 8;
#pragma unroll
        for (int ks = 0; ks < 4; ks++) {
            int c = ks * 16 + tg * 2;
            float2 x0 = *(const float2*)(smem + OFF_Q + r0 * 68 + c);
            float2 x1 = *(const float2*)(smem + OFF_Q + r1 * 68 + c);
            float2 x2 = *(const float2*)(smem + OFF_Q + r0 * 68 + c + 8);
            float2 x3 = *(const float2*)(smem + OFF_Q + r1 * 68 + c + 8);
            cvt_hilo2_f16(x0.x, x0.y, qah[m][ks][0], qal[m][ks][0]);
            cvt_hilo2_f16(x1.x, x1.y, qah[m][ks][1], qal[m][ks][1]);
            cvt_hilo2_f16(x2.x, x2.y, qah[m][ks][2], qal[m][ks][2]);
            cvt_hilo2_f16(x3.x, x3.y, qah[m][ks][3], qal[m][ks][3]);
        }
    }

    float rs[4] = {0.f, 0.f, 0.f, 0.f};
    float O[16][4];
#pragma unroll
    for (int j = 0; j < 16; j++) { O[j][0] = O[j][1] = O[j][2] = O[j][3] = 0.f; }

    // mask word pointers (one broadcast word per row per stage) and p_attn rows
    const unsigned* mp[4];
    float* pa[4];
#pragma unroll
    for (int r = 0; r < 4; r++) {
        int row = (r >> 1) * 16 + g + (r & 1) * 8;    // g, g+8, 16+g, 24+g
        mp[r] = g_mpack + (size_t)(q0 + row) * 64 + (warp >> 1);
        pa[r] = p_attn + ((size_t)bh * S_LEN + q0 + row) * S_LEN;
    }
    const unsigned posbase = (warp & 1) * 16;
    const size_t bh_base = (size_t)bh * S_LEN * KVSTR;

    // ---- prologue: issue stage 0 loads (Kh + Vh) ----
    {
        for (int i = tid; i < ARR_W / 4; i += 256) {
            unsigned so = (unsigned)(OFF_BUF * 4 + i * 16);
            CP_ASYNC16(smem_u32 + so,             (const uint4*)(g_Kh + bh_base) + i);
            CP_ASYNC16(smem_u32 + so + ARR_W * 4, (const uint4*)(g_Vh + bh_base) + i);
        }
        CP_COMMIT();
    }

    // =================== pipelined main loop: 16 stages of 128 tokens ==========
    for (int st = 0; st < 16; st++) {
        const int kb0 = st * 128;
        const unsigned bufoff = (unsigned)(st & 1) * (BUF_W * 4);

        CP_WAIT0();
        __syncthreads();   // stage-st data visible; prev compute done

        // ---- prefetch stage st+1 into the other buffer ----
        if (st < 15) {
            const size_t sb = bh_base + (size_t)(kb0 + 128) * KVSTR;
            const unsigned dst = (unsigned)(OFF_BUF * 4) + (unsigned)((st + 1) & 1) * (BUF_W * 4);
            for (int i = tid; i < ARR_W / 4; i += 256) {
                unsigned so = dst + (unsigned)i * 16u;
                CP_ASYNC16(smem_u32 + so,             (const uint4*)(g_Kh + sb) + i);
                CP_ASYNC16(smem_u32 + so + ARR_W * 4, (const uint4*)(g_Vh + sb) + i);
            }
            CP_COMMIT();
        }

        // ---- QK^T: 2 M-tiles x warp's 16 tokens, 2-term (Qh + Ql)·Kh ----
        float C00[4] = {0,0,0,0}, C01[4] = {0,0,0,0};
        float C10[4] = {0,0,0,0}, C11[4] = {0,0,0,0};
#pragma unroll
        for (int ks = 0; ks < 4; ks++) {
            unsigned b0, b1, b2, b3;
            LDSM_X4(b0, b1, b2, b3, kh_base + bufoff + ks * 32u);
            MMA16816(C00, qah[0][ks][0], qah[0][ks][1], qah[0][ks][2], qah[0][ks][3], b0, b1);
            MMA16816(C01, qah[0][ks][0], qah[0][ks][1], qah[0][ks][2], qah[0][ks][3], b2, b3);
            MMA16816(C10, qah[1][ks][0], qah[1][ks][1], qah[1][ks][2], qah[1][ks][3], b0, b1);
            MMA16816(C11, qah[1][ks][0], qah[1][ks][1], qah[1][ks][2], qah[1][ks][3], b2, b3);
            MMA16816(C00, qal[0][ks][0], qal[0][ks][1], qal[0][ks][2], qal[0][ks][3], b0, b1);
            MMA16816(C01, qal[0][ks][0], qal[0][ks][1], qal[0][ks][2], qal[0][ks][3], b2, b3);
            MMA16816(C10, qal[1][ks][0], qal[1][ks][1], qal[1][ks][2], qal[1][ks][3], b0, b1);
            MMA16816(C11, qal[1][ks][0], qal[1][ks][1], qal[1][ks][2], qal[1][ks][3], b2, b3);
        }

        // ---- epilogue: mask(bit), exp, rowsum; unnormalized exp -> p_attn (L2) ----
        unsigned mw0 = __ldg(mp[0] + st * 4);
        unsigned mw1 = __ldg(mp[1] + st * 4);
        unsigned mw2 = __ldg(mp[2] + st * 4);
        unsigned mw3 = __ldg(mp[3] + st * 4);
        float e[2][2][4];
#pragma unroll
        for (int m = 0; m < 2; m++) {
            unsigned ma = m ? mw2 : mw0;   // row m*16+g
            unsigned mb = m ? mw3 : mw1;   // row m*16+g+8
#pragma unroll
            for (int t = 0; t < 2; t++) {
                const float* C = m ? (t ? C11 : C10) : (t ? C01 : C00);
                int nb = kb0 + ln0 + t * 8 + tg * 2;
                unsigned sh = posbase + t * 8 + tg * 2;
                float* E = e[m][t];
                E[0] = ((ma >> sh) & 1u)       ? 0.f : __expf(C[0] * 0.125f);
                E[1] = ((ma >> (sh + 1)) & 1u) ? 0.f : __expf(C[1] * 0.125f);
                E[2] = ((mb >> sh) & 1u)       ? 0.f : __expf(C[2] * 0.125f);
                E[3] = ((mb >> (sh + 1)) & 1u) ? 0.f : __expf(C[3] * 0.125f);
                rs[2 * m]     += E[0] + E[1];
                rs[2 * m + 1] += E[2] + E[3];
                *(float2*)(pa[2 * m]     + nb) = make_float2(E[0], E[1]);   // stays in L2
                *(float2*)(pa[2 * m + 1] + nb) = make_float2(E[2], E[3]);
            }
        }

        // ---- E -> A-frag fp16 (1-term PV) ----
        unsigned Ah[2][4];
#pragma unroll
        for (int m = 0; m < 2; m++) {
            Ah[m][0] = cvt_h2(e[m][0][0], e[m][0][1]);
            Ah[m][1] = cvt_h2(e[m][0][2], e[m][0][3]);
            Ah[m][2] = cvt_h2(e[m][1][0], e[m][1][1]);
            Ah[m][3] = cvt_h2(e[m][1][2], e[m][1][3]);
        }

        // ---- PV: warp's 16 tokens x all 64 d, 1-term Ph·Vh ----
#pragma unroll
        for (int jp = 0; jp < 4; jp++) {
            unsigned b0, b1, b2, b3;
            LDSM_X4_T(b0, b1, b2, b3, vh_base + bufoff + jp * 32u);
#pragma unroll
            for (int m = 0; m < 2; m++) {
                MMA16816(O[m * 8 + 2 * jp],     Ah[m][0], Ah[m][1], Ah[m][2], Ah[m][3], b0, b1);
                MMA16816(O[m * 8 + 2 * jp + 1], Ah[m][0], Ah[m][1], Ah[m][2], Ah[m][3], b2, b3);
            }
        }
    }

    // ================= rowsums ================================================
#pragma unroll
    for (int r = 0; r < 4; r++) {
        rs[r] += __shfl_xor_sync(0xffffffff, rs[r], 1);
        rs[r] += __shfl_xor_sync(0xffffffff, rs[r], 2);
    }

    __syncthreads();   // last-stage LDSM reads done before O-red overlays buffers

    if (tg == 0) {
#pragma unroll
        for (int r = 0; r < 4; r++) {
            int row = (r >> 1) * 16 + g + (r & 1) * 8;
            smem[OFF_PART + row * 8 + warp] = rs[r];
        }
    }
    {
        float* base = smem + OFF_RED + warp * (32 * REDSTR);
#pragma unroll
        for (int m = 0; m < 2; m++) {
            int r0 = m * 16 + g, r1 = m * 16 + g + 8;
#pragma unroll
            for (int j = 0; j < 8; j++) {
                const float* Oj = O[m * 8 + j];
                *(float2*)(base + r0 * REDSTR + j * 8 + 2 * tg) = make_float2(Oj[0], Oj[1]);
                *(float2*)(base + r1 * REDSTR + j * 8 + 2 * tg) = make_float2(Oj[2], Oj[3]);
            }
        }
    }
    __syncthreads();

    if (tid < TQ) {
        float s = 0.f;
#pragma unroll
        for (int i = 0; i < 8; i++) s += smem[OFF_PART + tid * 8 + i];
        smem[OFF_INV + tid] = 1.0f / s;
    }
    __syncthreads();

    // ================= reduce O partials, write p_val =========================
#pragma unroll
    for (int it = 0; it < 2; it++) {
        int item = tid + it * 256;       // 0..511
        int row = item >> 4;
        int d0  = (item & 15) * 4;
        float4 acc = make_float4(0.f, 0.f, 0.f, 0.f);
#pragma unroll
        for (int w = 0; w < 8; w++) {
            float4 v = *(const float4*)(smem + OFF_RED + w * (32 * REDSTR) + row * REDSTR + d0);
            acc.x += v.x; acc.y += v.y; acc.z += v.z; acc.w += v.w;
        }
        float inv = smem[OFF_INV + row];
        acc.x *= inv; acc.y *= inv; acc.z *= inv; acc.w *= inv;
        *(float4*)(p_val + ((size_t)bh * S_LEN + q0 + row) * D_DIM + d0) = acc;
    }

    // ================= in-kernel normalize: L2 readback of own slice ==========
    // This CTA's 32 p_attn rows are contiguous: 32*2048 floats = 16384 float4.
    // They were just written (L2-resident). __syncthreads above orders the
    // unnormalized stores and smem inv for all threads in this CTA.
    {
        float4* slice = (float4*)(p_attn + ((size_t)bh * S_LEN + q0) * S_LEN);
#pragma unroll 8
        for (int i = 0; i < 64; i++) {
            int idx = tid + i * 256;          // 0..16383
            int row = idx >> 9;               // 512 float4 per row
            float inv = smem[OFF_INV + row];
            float4 v = __ldcg(slice + idx);
            v.x *= inv; v.y *= inv; v.z *= inv; v.w *= inv;
            __stcs(slice + idx, v);
        }
    }
}

extern "C" void kernel_launch(void* const* d_in, const int* in_sizes, int n_in,
                              void* d_out, int out_size)
{
    const float*    Q = (const float*)d_in[0];
    const float*    K = (const float*)d_in[1];
    const float*    V = (const float*)d_in[2];
    const unsigned* M = (const unsigned*)d_in[3];

    float* p_val  = (float*)d_out;
    float* p_attn = (float*)d_out + (size_t)2 * 16 * 2048 * 64;

    const size_t smem_bytes = (size_t)SMEM_WORDS * sizeof(float);  // 83584
    cudaFuncSetAttribute(attn_flash_kernel,
                         cudaFuncAttributeMaxDynamicSharedMemorySize,
                         (int)smem_bytes);

    preconvert_kv<<<dim3(128, NBH), 256>>>(K, V);
    pack_mask<<<512, 256>>>(M);
    attn_flash_kernel<<<dim3(S_LEN / TQ, NBH), 256, smem_bytes>>>(Q, p_val, p_attn);
}

// round 14
// speedup vs baseline: 1.8867x; 1.0998x over previous
#include <cuda_runtime.h>
#include <cuda_fp16.h>
#include <math.h>

#define S_LEN   2048
#define D_DIM   64
#define TQ      32
#define NBH     32
#define KVSTR   36        // u32 words per token row (32 data + 4 pad; LDSM-clean)
#define REDSTR  68
#define STFSTR  1036      // u32 (half2) words per Stile row; 12g mod 32 pattern -> conflict-free

// ---- main-kernel shared memory word offsets ----
#define OFF_Q    0                     // 32*68 = 2176
#define OFF_STF  2176                  // fp16 Stile: 32*1036 = 33152 u32 words
#define ARR_W    4608                  // 128 tokens * 36 words
#define BUF_W    (2*ARR_W)             // Kh,Vh = 9216 words per buffer
#define OFF_BUF  35328                 // two buffers: 2*9216 = 18432
#define OFF_PART (OFF_BUF + 2*BUF_W)   // 53760 : 32*8
#define OFF_INV  (OFF_PART + 256)      // 54016 : 32
#define SMEM_WORDS (OFF_INV + 32)      // 54048 words = 216192 bytes
#define OFF_RED  OFF_BUF               // O-reduction overlay: 8*32*68 = 17408 <= 18432

// ---- global scratch (single-fp16 K and V, token-row layout) ----
__device__ __align__(16) unsigned g_Kh[(size_t)NBH * S_LEN * KVSTR];
__device__ __align__(16) unsigned g_Vh[(size_t)NBH * S_LEN * KVSTR];
__device__ unsigned g_mpack[(size_t)S_LEN * (S_LEN / 32)];   // 1 bit per mask elem

static __device__ __forceinline__ unsigned cvt_h2(float x, float y) {
    __half2 hh = __floats2half2_rn(x, y);
    return *reinterpret_cast<unsigned*>(&hh);
}
static __device__ __forceinline__ void cvt_hilo2_f16(float x, float y, unsigned &h, unsigned &l) {
    __half2 hh = __floats2half2_rn(x, y);
    float rx = x - __half2float(__low2half(hh));
    float ry = y - __half2float(__high2half(hh));
    __half2 ll = __floats2half2_rn(rx, ry);
    h = *reinterpret_cast<unsigned*>(&hh);
    l = *reinterpret_cast<unsigned*>(&ll);
}

#define MMA16816(C, A0, A1, A2, A3, B0, B1)                                        \
    asm volatile("mma.sync.aligned.m16n8k16.row.col.f32.f16.f16.f32 "              \
                 "{%0,%1,%2,%3},{%4,%5,%6,%7},{%8,%9},{%0,%1,%2,%3};\n"            \
                 : "+f"(C[0]), "+f"(C[1]), "+f"(C[2]), "+f"(C[3])                  \
                 : "r"(A0), "r"(A1), "r"(A2), "r"(A3), "r"(B0), "r"(B1))

#define LDSM_X4(R0, R1, R2, R3, ADDR)                                              \
    asm volatile("ldmatrix.sync.aligned.m8n8.x4.shared.b16 {%0,%1,%2,%3}, [%4];"  \
                 : "=r"(R0), "=r"(R1), "=r"(R2), "=r"(R3) : "r"(ADDR))

#define LDSM_X4_T(R0, R1, R2, R3, ADDR)                                            \
    asm volatile("ldmatrix.sync.aligned.m8n8.x4.trans.shared.b16 {%0,%1,%2,%3}, [%4];" \
                 : "=r"(R0), "=r"(R1), "=r"(R2), "=r"(R3) : "r"(ADDR))

#define CP_ASYNC16(SADDR, GPTR)                                                    \
    asm volatile("cp.async.cg.shared.global [%0], [%1], 16;\n" :: "r"(SADDR), "l"(GPTR))
#define CP_COMMIT()  asm volatile("cp.async.commit_group;\n")
#define CP_WAIT0()   asm volatile("cp.async.wait_group 0;\n" ::: "memory")

// ===================== pre-pass 1: convert K,V -> fp16 scratch ==================
__global__ void __launch_bounds__(256)
preconvert_kv(const float* __restrict__ K, const float* __restrict__ V)
{
    const int bh  = blockIdx.y;
    const int idx = blockIdx.x * 256 + threadIdx.x;
    const int token = idx >> 4, c4 = idx & 15;
    const size_t tok = (size_t)bh * S_LEN + token;
    const size_t go  = tok * KVSTR + c4 * 2;

    float4 k = __ldg((const float4*)(K + tok * D_DIM) + c4);
    *(uint2*)&g_Kh[go] = make_uint2(cvt_h2(k.x, k.y), cvt_h2(k.z, k.w));
    float4 v = __ldg((const float4*)(V + tok * D_DIM) + c4);
    *(uint2*)&g_Vh[go] = make_uint2(cvt_h2(v.x, v.y), cvt_h2(v.z, v.w));
}

// ===================== pre-pass 2: pack mask to 1 bit/elem ======================
__global__ void __launch_bounds__(256)
pack_mask(const unsigned* __restrict__ M)
{
    const int lane = threadIdx.x & 31;
    const int wglob = (blockIdx.x * 256 + threadIdx.x) >> 5;
    const int nwarps = (gridDim.x * 256) >> 5;
    for (int w = wglob; w < S_LEN * (S_LEN / 32); w += nwarps) {
        unsigned bit = (M[(size_t)w * 32 + lane] != 0u) ? 1u : 0u;
        unsigned word = __ballot_sync(0xffffffffu, bit);
        if (lane == 0) g_mpack[w] = word;
    }
}

// ===================== main fused attention kernel ==============================
__global__ void __launch_bounds__(256, 1)
attn_flash_kernel(const float* __restrict__ Q,
                  float* __restrict__ p_val,
                  float* __restrict__ p_attn)
{
    extern __shared__ float smem[];
    unsigned* smw = reinterpret_cast<unsigned*>(smem);
    const unsigned smem_u32 = (unsigned)__cvta_generic_to_shared(smem);

    const int tid  = threadIdx.x;
    const int warp = tid >> 5;
    const int lane = tid & 31;
    const int g    = lane >> 2;
    const int tg   = lane & 3;
    const int bh   = blockIdx.y;
    const int q0   = blockIdx.x * TQ;
    const int ln0  = warp * 16;

    // ---- ldmatrix per-lane byte addresses (buffer 0) ----
    const int qk_row  = ln0 + ((lane >> 4) << 3) + (lane & 7);
    const unsigned qk_off = (unsigned)(qk_row * KVSTR + (((lane >> 3) & 1) << 2)) * 4u;
    const unsigned kh_base = smem_u32 + OFF_BUF * 4u + qk_off;
    const int pv_row  = ln0 + (((lane >> 3) & 1) << 3) + (lane & 7);
    const unsigned pv_off = (unsigned)(pv_row * KVSTR + ((lane >> 4) << 2)) * 4u;
    const unsigned vh_base = smem_u32 + (OFF_BUF + ARR_W) * 4u + pv_off;

    // ================= Q tile (32 rows) -> smem -> A fragments (hi/lo fp16) ====
    {
#pragma unroll
        for (int i = 0; i < 2; i++) {
            int idx = tid + i * 256;
            int row = idx >> 4, c4 = idx & 15;
            float4 qv = __ldg((const float4*)(Q + ((size_t)bh * S_LEN + q0 + row) * D_DIM) + c4);
            *((float4*)(smem + OFF_Q + row * 68 + c4 * 4)) = qv;
        }
    }
    __syncthreads();

    unsigned qah[2][4][4], qal[2][4][4];
#pragma unroll
    for (int m = 0; m < 2; m++) {
        int r0 = m * 16 + g, r1 = m * 16 + g + 8;
#pragma unroll
        for (int ks = 0; ks < 4; ks++) {
            int c = ks * 16 + tg * 2;
            float2 x0 = *(const float2*)(smem + OFF_Q + r0 * 68 + c);
            float2 x1 = *(const float2*)(smem + OFF_Q + r1 * 68 + c);
            float2 x2 = *(const float2*)(smem + OFF_Q + r0 * 68 + c + 8);
            float2 x3 = *(const float2*)(smem + OFF_Q + r1 * 68 + c + 8);
            cvt_hilo2_f16(x0.x, x0.y, qah[m][ks][0], qal[m][ks][0]);
            cvt_hilo2_f16(x1.x, x1.y, qah[m][ks][1], qal[m][ks][1]);
            cvt_hilo2_f16(x2.x, x2.y, qah[m][ks][2], qal[m][ks][2]);
            cvt_hilo2_f16(x3.x, x3.y, qah[m][ks][3], qal[m][ks][3]);
        }
    }

    float rs[4] = {0.f, 0.f, 0.f, 0.f};
    float O[16][4];
#pragma unroll
    for (int j = 0; j < 16; j++) { O[j][0] = O[j][1] = O[j][2] = O[j][3] = 0.f; }

    // mask word pointers (one broadcast word per row per stage)
    const unsigned* mp[4];
#pragma unroll
    for (int r = 0; r < 4; r++) {
        int row = (r >> 1) * 16 + g + (r & 1) * 8;    // g, g+8, 16+g, 24+g
        mp[r] = g_mpack + (size_t)(q0 + row) * 64 + (warp >> 1);
    }
    const unsigned posbase = (warp & 1) * 16;
    const size_t bh_base = (size_t)bh * S_LEN * KVSTR;
    unsigned* stf = smw + OFF_STF;

    // ---- prologue: issue stage 0 loads (Kh + Vh) ----
    {
        for (int i = tid; i < ARR_W / 4; i += 256) {
            unsigned so = (unsigned)(OFF_BUF * 4 + i * 16);
            CP_ASYNC16(smem_u32 + so,             (const uint4*)(g_Kh + bh_base) + i);
            CP_ASYNC16(smem_u32 + so + ARR_W * 4, (const uint4*)(g_Vh + bh_base) + i);
        }
        CP_COMMIT();
    }

    // =================== pipelined main loop: 16 stages of 128 tokens ==========
    for (int st = 0; st < 16; st++) {
        const int kb0 = st * 128;
        const unsigned bufoff = (unsigned)(st & 1) * (BUF_W * 4);

        CP_WAIT0();
        __syncthreads();   // stage-st data visible; prev compute done

        // ---- prefetch stage st+1 into the other buffer ----
        if (st < 15) {
            const size_t sb = bh_base + (size_t)(kb0 + 128) * KVSTR;
            const unsigned dst = (unsigned)(OFF_BUF * 4) + (unsigned)((st + 1) & 1) * (BUF_W * 4);
            for (int i = tid; i < ARR_W / 4; i += 256) {
                unsigned so = dst + (unsigned)i * 16u;
                CP_ASYNC16(smem_u32 + so,             (const uint4*)(g_Kh + sb) + i);
                CP_ASYNC16(smem_u32 + so + ARR_W * 4, (const uint4*)(g_Vh + sb) + i);
            }
            CP_COMMIT();
        }

        // ---- QK^T: 2 M-tiles x warp's 16 tokens, 2-term (Qh + Ql)·Kh ----
        float C00[4] = {0,0,0,0}, C01[4] = {0,0,0,0};
        float C10[4] = {0,0,0,0}, C11[4] = {0,0,0,0};
#pragma unroll
        for (int ks = 0; ks < 4; ks++) {
            unsigned b0, b1, b2, b3;
            LDSM_X4(b0, b1, b2, b3, kh_base + bufoff + ks * 32u);
            MMA16816(C00, qah[0][ks][0], qah[0][ks][1], qah[0][ks][2], qah[0][ks][3], b0, b1);
            MMA16816(C01, qah[0][ks][0], qah[0][ks][1], qah[0][ks][2], qah[0][ks][3], b2, b3);
            MMA16816(C10, qah[1][ks][0], qah[1][ks][1], qah[1][ks][2], qah[1][ks][3], b0, b1);
            MMA16816(C11, qah[1][ks][0], qah[1][ks][1], qah[1][ks][2], qah[1][ks][3], b2, b3);
            MMA16816(C00, qal[0][ks][0], qal[0][ks][1], qal[0][ks][2], qal[0][ks][3], b0, b1);
            MMA16816(C01, qal[0][ks][0], qal[0][ks][1], qal[0][ks][2], qal[0][ks][3], b2, b3);
            MMA16816(C10, qal[1][ks][0], qal[1][ks][1], qal[1][ks][2], qal[1][ks][3], b0, b1);
            MMA16816(C11, qal[1][ks][0], qal[1][ks][1], qal[1][ks][2], qal[1][ks][3], b2, b3);
        }

        // ---- epilogue: mask(bit), exp, rowsum ----
        unsigned mw0 = __ldg(mp[0] + st * 4);
        unsigned mw1 = __ldg(mp[1] + st * 4);
        unsigned mw2 = __ldg(mp[2] + st * 4);
        unsigned mw3 = __ldg(mp[3] + st * 4);
        float e[2][2][4];
#pragma unroll
        for (int m = 0; m < 2; m++) {
            unsigned ma = m ? mw2 : mw0;   // row m*16+g
            unsigned mb = m ? mw3 : mw1;   // row m*16+g+8
#pragma unroll
            for (int t = 0; t < 2; t++) {
                const float* C = m ? (t ? C11 : C10) : (t ? C01 : C00);
                unsigned sh = posbase + t * 8 + tg * 2;
                float* E = e[m][t];
                E[0] = ((ma >> sh) & 1u)       ? 0.f : __expf(C[0] * 0.125f);
                E[1] = ((ma >> (sh + 1)) & 1u) ? 0.f : __expf(C[1] * 0.125f);
                E[2] = ((mb >> sh) & 1u)       ? 0.f : __expf(C[2] * 0.125f);
                E[3] = ((mb >> (sh + 1)) & 1u) ? 0.f : __expf(C[3] * 0.125f);
                rs[2 * m]     += E[0] + E[1];
                rs[2 * m + 1] += E[2] + E[3];
            }
        }

        // ---- E -> A-frag fp16; also store to fp16 Stile (smem) ----
        const int colw = st * 64 + warp * 8 + tg;    // half2 word column
        unsigned Ah[2][4];
#pragma unroll
        for (int m = 0; m < 2; m++) {
            Ah[m][0] = cvt_h2(e[m][0][0], e[m][0][1]);
            Ah[m][1] = cvt_h2(e[m][0][2], e[m][0][3]);
            Ah[m][2] = cvt_h2(e[m][1][0], e[m][1][1]);
            Ah[m][3] = cvt_h2(e[m][1][2], e[m][1][3]);
            unsigned* r0 = stf + (m * 16 + g) * STFSTR;
            unsigned* r1 = stf + (m * 16 + g + 8) * STFSTR;
            r0[colw]     = Ah[m][0];
            r1[colw]     = Ah[m][1];
            r0[colw + 4] = Ah[m][2];
            r1[colw + 4] = Ah[m][3];
        }

        // ---- PV: warp's 16 tokens x all 64 d, 1-term Ph·Vh ----
#pragma unroll
        for (int jp = 0; jp < 4; jp++) {
            unsigned b0, b1, b2, b3;
            LDSM_X4_T(b0, b1, b2, b3, vh_base + bufoff + jp * 32u);
#pragma unroll
            for (int m = 0; m < 2; m++) {
                MMA16816(O[m * 8 + 2 * jp],     Ah[m][0], Ah[m][1], Ah[m][2], Ah[m][3], b0, b1);
                MMA16816(O[m * 8 + 2 * jp + 1], Ah[m][0], Ah[m][1], Ah[m][2], Ah[m][3], b2, b3);
            }
        }
    }

    // ================= rowsums ================================================
#pragma unroll
    for (int r = 0; r < 4; r++) {
        rs[r] += __shfl_xor_sync(0xffffffff, rs[r], 1);
        rs[r] += __shfl_xor_sync(0xffffffff, rs[r], 2);
    }

    __syncthreads();   // last-stage LDSM reads done before O-red overlays buffers

    if (tg == 0) {
#pragma unroll
        for (int r = 0; r < 4; r++) {
            int row = (r >> 1) * 16 + g + (r & 1) * 8;
            smem[OFF_PART + row * 8 + warp] = rs[r];
        }
    }
    {
        float* base = smem + OFF_RED + warp * (32 * REDSTR);
#pragma unroll
        for (int m = 0; m < 2; m++) {
            int r0 = m * 16 + g, r1 = m * 16 + g + 8;
#pragma unroll
            for (int j = 0; j < 8; j++) {
                const float* Oj = O[m * 8 + j];
                *(float2*)(base + r0 * REDSTR + j * 8 + 2 * tg) = make_float2(Oj[0], Oj[1]);
                *(float2*)(base + r1 * REDSTR + j * 8 + 2 * tg) = make_float2(Oj[2], Oj[3]);
            }
        }
    }
    __syncthreads();

    if (tid < TQ) {
        float s = 0.f;
#pragma unroll
        for (int i = 0; i < 8; i++) s += smem[OFF_PART + tid * 8 + i];
        smem[OFF_INV + tid] = 1.0f / s;
    }
    __syncthreads();

    // ================= reduce O partials, write p_val =========================
#pragma unroll
    for (int it = 0; it < 2; it++) {
        int item = tid + it * 256;       // 0..511
        int row = item >> 4;
        int d0  = (item & 15) * 4;
        float4 acc = make_float4(0.f, 0.f, 0.f, 0.f);
#pragma unroll
        for (int w = 0; w < 8; w++) {
            float4 v = *(const float4*)(smem + OFF_RED + w * (32 * REDSTR) + row * REDSTR + d0);
            acc.x += v.x; acc.y += v.y; acc.z += v.z; acc.w += v.w;
        }
        float inv = smem[OFF_INV + row];
        acc.x *= inv; acc.y *= inv; acc.z *= inv; acc.w *= inv;
        *(float4*)(p_val + ((size_t)bh * S_LEN + q0 + row) * D_DIM + d0) = acc;
    }

    // ================= write normalized p_attn from fp16 Stile ================
    {
        float* out = p_attn + ((size_t)bh * S_LEN + q0) * S_LEN;
#pragma unroll 8
        for (int i = 0; i < 64; i++) {
            int idx = tid + i * 256;          // 0..16383 float4 units
            int row = idx >> 9;               // 512 float4 per row
            int c4  = idx & 511;
            uint2 hw = *(const uint2*)(stf + row * STFSTR + c4 * 2);
            __half2 a = *reinterpret_cast<__half2*>(&hw.x);
            __half2 b = *reinterpret_cast<__half2*>(&hw.y);
            float inv = smem[OFF_INV + row];
            float4 v = make_float4(__low2float(a) * inv, __high2float(a) * inv,
                                   __low2float(b) * inv, __high2float(b) * inv);
            __stcs((float4*)(out + (size_t)row * S_LEN) + c4, v);
        }
    }
}

extern "C" void kernel_launch(void* const* d_in, const int* in_sizes, int n_in,
                              void* d_out, int out_size)
{
    const float*    Q = (const float*)d_in[0];
    const float*    K = (const float*)d_in[1];
    const float*    V = (const float*)d_in[2];
    const unsigned* M = (const unsigned*)d_in[3];

    float* p_val  = (float*)d_out;
    float* p_attn = (float*)d_out + (size_t)2 * 16 * 2048 * 64;

    const size_t smem_bytes = (size_t)SMEM_WORDS * sizeof(float);  // 216192
    cudaFuncSetAttribute(attn_flash_kernel,
                         cudaFuncAttributeMaxDynamicSharedMemorySize,
                         (int)smem_bytes);

    preconvert_kv<<<dim3(128, NBH), 256>>>(K, V);
    pack_mask<<<512, 256>>>(M);
    attn_flash_kernel<<<dim3(S_LEN / TQ, NBH), 256, smem_bytes>>>(Q, p_val, p_attn);
}

// round 15
// speedup vs baseline: 2.0026x; 1.0615x over previous
#include <cuda_runtime.h>
#include <cuda_fp16.h>
#include <math.h>

#define S_LEN   2048
#define D_DIM   64
#define TQ      32
#define NBH     32
#define NTHR    512
#define KVSTR   36        // u32 words per token row (32 data + 4 pad; LDSM-clean)
#define REDSTR  68
#define STFSTR  1036      // u32 (half2) words per Stile row

// ---- main-kernel shared memory word offsets ----
#define OFF_Q    0                     // 32*68 = 2176
#define OFF_STF  2176                  // fp16 Stile: 32*1036 = 33152 u32 words
#define ARR_W    4608                  // 128 tokens * 36 words
#define BUF_W    (2*ARR_W)             // Kh,Vh = 9216 words per buffer
#define OFF_BUF  35328                 // two buffers: 2*9216 = 18432
#define OFF_PART (OFF_BUF + 2*BUF_W)   // 53760 : 32 rows * 8 warps
#define OFF_INV  (OFF_PART + 256)      // 54016 : 32
#define SMEM_WORDS (OFF_INV + 32)      // 54048 words = 216192 bytes
#define OFF_RED  OFF_BUF               // O-reduction overlay: 16 warps*16 rows*68 = 17408 <= 18432

// ---- global scratch (single-fp16 K and V, token-row layout) ----
__device__ __align__(16) unsigned g_Kh[(size_t)NBH * S_LEN * KVSTR];
__device__ __align__(16) unsigned g_Vh[(size_t)NBH * S_LEN * KVSTR];
__device__ unsigned g_mpack[(size_t)S_LEN * (S_LEN / 32)];   // 1 bit per mask elem

static __device__ __forceinline__ unsigned cvt_h2(float x, float y) {
    __half2 hh = __floats2half2_rn(x, y);
    return *reinterpret_cast<unsigned*>(&hh);
}
static __device__ __forceinline__ void cvt_hilo2_f16(float x, float y, unsigned &h, unsigned &l) {
    __half2 hh = __floats2half2_rn(x, y);
    float rx = x - __half2float(__low2half(hh));
    float ry = y - __half2float(__high2half(hh));
    __half2 ll = __floats2half2_rn(rx, ry);
    h = *reinterpret_cast<unsigned*>(&hh);
    l = *reinterpret_cast<unsigned*>(&ll);
}

#define MMA16816(C, A0, A1, A2, A3, B0, B1)                                        \
    asm volatile("mma.sync.aligned.m16n8k16.row.col.f32.f16.f16.f32 "              \
                 "{%0,%1,%2,%3},{%4,%5,%6,%7},{%8,%9},{%0,%1,%2,%3};\n"            \
                 : "+f"(C[0]), "+f"(C[1]), "+f"(C[2]), "+f"(C[3])                  \
                 : "r"(A0), "r"(A1), "r"(A2), "r"(A3), "r"(B0), "r"(B1))

#define LDSM_X4(R0, R1, R2, R3, ADDR)                                              \
    asm volatile("ldmatrix.sync.aligned.m8n8.x4.shared.b16 {%0,%1,%2,%3}, [%4];"  \
                 : "=r"(R0), "=r"(R1), "=r"(R2), "=r"(R3) : "r"(ADDR))

#define LDSM_X4_T(R0, R1, R2, R3, ADDR)                                            \
    asm volatile("ldmatrix.sync.aligned.m8n8.x4.trans.shared.b16 {%0,%1,%2,%3}, [%4];" \
                 : "=r"(R0), "=r"(R1), "=r"(R2), "=r"(R3) : "r"(ADDR))

#define CP_ASYNC16(SADDR, GPTR)                                                    \
    asm volatile("cp.async.cg.shared.global [%0], [%1], 16;\n" :: "r"(SADDR), "l"(GPTR))
#define CP_COMMIT()  asm volatile("cp.async.commit_group;\n")
#define CP_WAIT0()   asm volatile("cp.async.wait_group 0;\n" ::: "memory")

// ===================== pre-pass 1: convert K,V -> fp16 scratch ==================
__global__ void __launch_bounds__(256)
preconvert_kv(const float* __restrict__ K, const float* __restrict__ V)
{
    const int bh  = blockIdx.y;
    const int idx = blockIdx.x * 256 + threadIdx.x;
    const int token = idx >> 4, c4 = idx & 15;
    const size_t tok = (size_t)bh * S_LEN + token;
    const size_t go  = tok * KVSTR + c4 * 2;

    float4 k = __ldg((const float4*)(K + tok * D_DIM) + c4);
    *(uint2*)&g_Kh[go] = make_uint2(cvt_h2(k.x, k.y), cvt_h2(k.z, k.w));
    float4 v = __ldg((const float4*)(V + tok * D_DIM) + c4);
    *(uint2*)&g_Vh[go] = make_uint2(cvt_h2(v.x, v.y), cvt_h2(v.z, v.w));
}

// ===================== pre-pass 2: pack mask to 1 bit/elem ======================
__global__ void __launch_bounds__(256)
pack_mask(const unsigned* __restrict__ M)
{
    const int lane = threadIdx.x & 31;
    const int wglob = (blockIdx.x * 256 + threadIdx.x) >> 5;
    const int nwarps = (gridDim.x * 256) >> 5;
    for (int w = wglob; w < S_LEN * (S_LEN / 32); w += nwarps) {
        unsigned bit = (M[(size_t)w * 32 + lane] != 0u) ? 1u : 0u;
        unsigned word = __ballot_sync(0xffffffffu, bit);
        if (lane == 0) g_mpack[w] = word;
    }
}

// ===================== main fused attention kernel (512 thr, 16 warps) ==========
__global__ void __launch_bounds__(NTHR, 1)
attn_flash_kernel(const float* __restrict__ Q,
                  float* __restrict__ p_val,
                  float* __restrict__ p_attn)
{
    extern __shared__ float smem[];
    unsigned* smw = reinterpret_cast<unsigned*>(smem);
    const unsigned smem_u32 = (unsigned)__cvta_generic_to_shared(smem);

    const int tid  = threadIdx.x;
    const int warp = tid >> 5;          // 0..15
    const int lane = tid & 31;
    const int g    = lane >> 2;
    const int tg   = lane & 3;
    const int m    = warp >> 3;         // m-half: rows m*16 .. m*16+15
    const int wi   = warp & 7;          // token-slice within stage
    const int bh   = blockIdx.y;
    const int q0   = blockIdx.x * TQ;
    const int ln0  = wi * 16;

    // ---- ldmatrix per-lane byte addresses (buffer 0) ----
    const int qk_row  = ln0 + ((lane >> 4) << 3) + (lane & 7);
    const unsigned qk_off = (unsigned)(qk_row * KVSTR + (((lane >> 3) & 1) << 2)) * 4u;
    const unsigned kh_base = smem_u32 + OFF_BUF * 4u + qk_off;
    const int pv_row  = ln0 + (((lane >> 3) & 1) << 3) + (lane & 7);
    const unsigned pv_off = (unsigned)(pv_row * KVSTR + ((lane >> 4) << 2)) * 4u;
    const unsigned vh_base = smem_u32 + (OFF_BUF + ARR_W) * 4u + pv_off;

    // ================= Q tile (32 rows) -> smem -> A fragments (hi/lo fp16) ====
    {
        int row = tid >> 4, c4 = tid & 15;   // 512 threads = 32 rows x 16 f4
        float4 qv = __ldg((const float4*)(Q + ((size_t)bh * S_LEN + q0 + row) * D_DIM) + c4);
        *((float4*)(smem + OFF_Q + row * 68 + c4 * 4)) = qv;
    }
    __syncthreads();

    unsigned qah[4][4], qal[4][4];
    {
        int r0 = m * 16 + g, r1 = m * 16 + g + 8;
#pragma unroll
        for (int ks = 0; ks < 4; ks++) {
            int c = ks * 16 + tg * 2;
            float2 x0 = *(const float2*)(smem + OFF_Q + r0 * 68 + c);
            float2 x1 = *(const float2*)(smem + OFF_Q + r1 * 68 + c);
            float2 x2 = *(const float2*)(smem + OFF_Q + r0 * 68 + c + 8);
            float2 x3 = *(const float2*)(smem + OFF_Q + r1 * 68 + c + 8);
            cvt_hilo2_f16(x0.x, x0.y, qah[ks][0], qal[ks][0]);
            cvt_hilo2_f16(x1.x, x1.y, qah[ks][1], qal[ks][1]);
            cvt_hilo2_f16(x2.x, x2.y, qah[ks][2], qal[ks][2]);
            cvt_hilo2_f16(x3.x, x3.y, qah[ks][3], qal[ks][3]);
        }
    }

    float rs0 = 0.f, rs1 = 0.f;
    float O[8][4];
#pragma unroll
    for (int j = 0; j < 8; j++) { O[j][0] = O[j][1] = O[j][2] = O[j][3] = 0.f; }

    // mask word pointers (rows m*16+g, m*16+g+8; warp's 16 tokens -> word wi>>1)
    const unsigned* mp0 = g_mpack + (size_t)(q0 + m * 16 + g) * 64 + (wi >> 1);
    const unsigned* mp1 = g_mpack + (size_t)(q0 + m * 16 + g + 8) * 64 + (wi >> 1);
    const unsigned posbase = (wi & 1) * 16;
    const size_t bh_base = (size_t)bh * S_LEN * KVSTR;
    unsigned* stf = smw + OFF_STF;

    // ---- prologue: issue stage 0 loads (Kh + Vh) ----
    {
        for (int i = tid; i < ARR_W / 4; i += NTHR) {
            unsigned so = (unsigned)(OFF_BUF * 4 + i * 16);
            CP_ASYNC16(smem_u32 + so,             (const uint4*)(g_Kh + bh_base) + i);
            CP_ASYNC16(smem_u32 + so + ARR_W * 4, (const uint4*)(g_Vh + bh_base) + i);
        }
        CP_COMMIT();
    }

    // =================== pipelined main loop: 16 stages of 128 tokens ==========
    for (int st = 0; st < 16; st++) {
        const int kb0 = st * 128;
        const unsigned bufoff = (unsigned)(st & 1) * (BUF_W * 4);

        CP_WAIT0();
        __syncthreads();   // stage-st data visible; prev compute done

        // ---- prefetch stage st+1 into the other buffer ----
        if (st < 15) {
            const size_t sb = bh_base + (size_t)(kb0 + 128) * KVSTR;
            const unsigned dst = (unsigned)(OFF_BUF * 4) + (unsigned)((st + 1) & 1) * (BUF_W * 4);
            for (int i = tid; i < ARR_W / 4; i += NTHR) {
                unsigned so = dst + (unsigned)i * 16u;
                CP_ASYNC16(smem_u32 + so,             (const uint4*)(g_Kh + sb) + i);
                CP_ASYNC16(smem_u32 + so + ARR_W * 4, (const uint4*)(g_Vh + sb) + i);
            }
            CP_COMMIT();
        }

        // ---- mask words early ----
        unsigned mw0 = __ldg(mp0 + st * 4);
        unsigned mw1 = __ldg(mp1 + st * 4);

        // ---- QK^T: 1 M-tile x warp's 16 tokens, 2-term (Qh + Ql)·Kh ----
        float C0[4] = {0,0,0,0}, C1[4] = {0,0,0,0};
#pragma unroll
        for (int ks = 0; ks < 4; ks++) {
            unsigned b0, b1, b2, b3;
            LDSM_X4(b0, b1, b2, b3, kh_base + bufoff + ks * 32u);
            MMA16816(C0, qah[ks][0], qah[ks][1], qah[ks][2], qah[ks][3], b0, b1);
            MMA16816(C1, qah[ks][0], qah[ks][1], qah[ks][2], qah[ks][3], b2, b3);
            MMA16816(C0, qal[ks][0], qal[ks][1], qal[ks][2], qal[ks][3], b0, b1);
            MMA16816(C1, qal[ks][0], qal[ks][1], qal[ks][2], qal[ks][3], b2, b3);
        }

        // ---- epilogue: mask(bit), exp, rowsum ----
        float e[2][4];
#pragma unroll
        for (int t = 0; t < 2; t++) {
            const float* C = t ? C1 : C0;
            unsigned sh = posbase + t * 8 + tg * 2;
            float* E = e[t];
            E[0] = ((mw0 >> sh) & 1u)       ? 0.f : __expf(C[0] * 0.125f);
            E[1] = ((mw0 >> (sh + 1)) & 1u) ? 0.f : __expf(C[1] * 0.125f);
            E[2] = ((mw1 >> sh) & 1u)       ? 0.f : __expf(C[2] * 0.125f);
            E[3] = ((mw1 >> (sh + 1)) & 1u) ? 0.f : __expf(C[3] * 0.125f);
            rs0 += E[0] + E[1];
            rs1 += E[2] + E[3];
        }

        // ---- E -> A-frag fp16; also store to fp16 Stile (smem) ----
        const int colw = st * 64 + wi * 8 + tg;    // half2 word column
        unsigned Ah[4];
        Ah[0] = cvt_h2(e[0][0], e[0][1]);
        Ah[1] = cvt_h2(e[0][2], e[0][3]);
        Ah[2] = cvt_h2(e[1][0], e[1][1]);
        Ah[3] = cvt_h2(e[1][2], e[1][3]);
        {
            unsigned* r0 = stf + (m * 16 + g) * STFSTR;
            unsigned* r1 = stf + (m * 16 + g + 8) * STFSTR;
            r0[colw]     = Ah[0];
            r1[colw]     = Ah[1];
            r0[colw + 4] = Ah[2];
            r1[colw + 4] = Ah[3];
        }

        // ---- PV: warp's 16 tokens x all 64 d, 1-term Ph·Vh ----
#pragma unroll
        for (int jp = 0; jp < 4; jp++) {
            unsigned b0, b1, b2, b3;
            LDSM_X4_T(b0, b1, b2, b3, vh_base + bufoff + jp * 32u);
            MMA16816(O[2 * jp],     Ah[0], Ah[1], Ah[2], Ah[3], b0, b1);
            MMA16816(O[2 * jp + 1], Ah[0], Ah[1], Ah[2], Ah[3], b2, b3);
        }
    }

    // ================= rowsums ================================================
    rs0 += __shfl_xor_sync(0xffffffff, rs0, 1);
    rs0 += __shfl_xor_sync(0xffffffff, rs0, 2);
    rs1 += __shfl_xor_sync(0xffffffff, rs1, 1);
    rs1 += __shfl_xor_sync(0xffffffff, rs1, 2);

    __syncthreads();   // last-stage LDSM reads done before O-red overlays buffers

    if (tg == 0) {
        smem[OFF_PART + (m * 16 + g) * 8 + wi]     = rs0;
        smem[OFF_PART + (m * 16 + g + 8) * 8 + wi] = rs1;
    }
    {
        float* base = smem + OFF_RED + warp * (16 * REDSTR);
#pragma unroll
        for (int j = 0; j < 8; j++) {
            *(float2*)(base + g * REDSTR + j * 8 + 2 * tg)       = make_float2(O[j][0], O[j][1]);
            *(float2*)(base + (g + 8) * REDSTR + j * 8 + 2 * tg) = make_float2(O[j][2], O[j][3]);
        }
    }
    __syncthreads();

    if (tid < TQ) {
        float s = 0.f;
#pragma unroll
        for (int i = 0; i < 8; i++) s += smem[OFF_PART + tid * 8 + i];
        smem[OFF_INV + tid] = 1.0f / s;
    }
    __syncthreads();

    // ================= reduce O partials, write p_val =========================
    {
        int row = tid >> 4;               // 0..31
        int d0  = (tid & 15) * 4;
        int mh  = row >> 4;               // which m-half
        int rl  = row & 15;               // local row within half
        float4 acc = make_float4(0.f, 0.f, 0.f, 0.f);
#pragma unroll
        for (int w = 0; w < 8; w++) {
            float4 v = *(const float4*)(smem + OFF_RED + (mh * 8 + w) * (16 * REDSTR) + rl * REDSTR + d0);
            acc.x += v.x; acc.y += v.y; acc.z += v.z; acc.w += v.w;
        }
        float inv = smem[OFF_INV + row];
        acc.x *= inv; acc.y *= inv; acc.z *= inv; acc.w *= inv;
        __stcs((float4*)(p_val + ((size_t)bh * S_LEN + q0 + row) * D_DIM + d0), acc);
    }

    // ================= write normalized p_attn from fp16 Stile ================
    {
        float* out = p_attn + ((size_t)bh * S_LEN + q0) * S_LEN;
#pragma unroll 8
        for (int i = 0; i < 32; i++) {
            int idx = tid + i * NTHR;         // 0..16383 float4 units
            int row = idx >> 9;               // 512 float4 per row
            int c4  = idx & 511;
            uint2 hw = *(const uint2*)(stf + row * STFSTR + c4 * 2);
            __half2 a = *reinterpret_cast<__half2*>(&hw.x);
            __half2 b = *reinterpret_cast<__half2*>(&hw.y);
            float inv = smem[OFF_INV + row];
            float4 v = make_float4(__low2float(a) * inv, __high2float(a) * inv,
                                   __low2float(b) * inv, __high2float(b) * inv);
            __stcs((float4*)(out + (size_t)row * S_LEN) + c4, v);
        }
    }
}

extern "C" void kernel_launch(void* const* d_in, const int* in_sizes, int n_in,
                              void* d_out, int out_size)
{
    const float*    Q = (const float*)d_in[0];
    const float*    K = (const float*)d_in[1];
    const float*    V = (const float*)d_in[2];
    const unsigned* M = (const unsigned*)d_in[3];

    float* p_val  = (float*)d_out;
    float* p_attn = (float*)d_out + (size_t)2 * 16 * 2048 * 64;

    const size_t smem_bytes = (size_t)SMEM_WORDS * sizeof(float);  // 216192
    cudaFuncSetAttribute(attn_flash_kernel,
                         cudaFuncAttributeMaxDynamicSharedMemorySize,
                         (int)smem_bytes);

    preconvert_kv<<<dim3(128, NBH), 256>>>(K, V);
    pack_mask<<<512, 256>>>(M);
    attn_flash_kernel<<<dim3(S_LEN / TQ, NBH), NTHR, smem_bytes>>>(Q, p_val, p_attn);
}